// round 7
// baseline (speedup 1.0000x reference)
#include <cuda_runtime.h>
#include <cstdint>
#include <cstddef>

#define DINL __device__ __forceinline__

// ------------------------- problem sizes -------------------------
#define NN 8192
#define KK 2048
#define DD 512
#define NH (NN - KK)   // 6144

// ------------------------- scratch (static device globals) -------------------------
__device__ char g_xq1[NN*DD],  g_xq0[NN*DD];
__device__ char g_s0q1[NN*KK], g_s0q0[NN*KK];
__device__ char g_s1q1[KK*NN], g_s1q0[KK*NN];
__device__ char g_s2q1[(size_t)NN*NH], g_s2q0[(size_t)NN*NH];
__device__ char g_s3q1[(size_t)NH*NN], g_s3q0[(size_t)NH*NN];
__device__ char g_Wt1[DD*DD],  g_Wt0[DD*DD];
__device__ char g_Pt1[DD*NN],  g_Pt0[DD*NN];
__device__ char g_T1t1[DD*KK], g_T1t0[DD*KK];
__device__ char g_T3t1[DD*NH], g_T3t0[DD*NH];
__device__ float g_P  [NN*DD];
__device__ float g_T1p[4*KK*DD];
__device__ float g_T3p[3*NH*DD];
__device__ float g_OL [NN*DD];
// scales
__device__ float g_sax[NN], g_sas0[NN], g_sas1[KK], g_sas2[NN], g_sas3[NH];
__device__ float g_sbW[DD], g_sbP[DD], g_sbT1[DD], g_sbT3[DD];
__device__ float g_cmW[DD], g_cmP[DD], g_cmT1[DD], g_cmT3[DD];

// ------------------------- ptx helpers (base ISA only) ----
DINL uint32_t smem_u32(const void* p) {
    uint32_t a;
    asm("{ .reg .u64 t; cvta.to.shared.u64 t, %1; cvt.u32.u64 %0, t; }" : "=r"(a) : "l"(p));
    return a;
}
DINL void cp16(uint32_t saddr, const void* g) {
    asm volatile("cp.async.cg.shared.global [%0], [%1], 16;" :: "r"(saddr), "l"(g));
}
DINL void cp_commit() { asm volatile("cp.async.commit_group;" ::: "memory"); }
DINL void cp_wait2()  { asm volatile("cp.async.wait_group 2;" ::: "memory"); }

DINL void ldsm4(uint32_t (&r)[4], uint32_t addr) {
    asm volatile("ldmatrix.sync.aligned.m8n8.x4.shared.b16 {%0,%1,%2,%3}, [%4];"
                 : "=r"(r[0]), "=r"(r[1]), "=r"(r[2]), "=r"(r[3]) : "r"(addr));
}
DINL void mma_s8(int (&d)[4], const uint32_t (&a)[4], const uint32_t* b) {
    asm volatile(
        "mma.sync.aligned.m16n8k32.row.col.s32.s8.s8.s32 "
        "{%0,%1,%2,%3}, {%4,%5,%6,%7}, {%8,%9}, {%0,%1,%2,%3};"
        : "+r"(d[0]), "+r"(d[1]), "+r"(d[2]), "+r"(d[3])
        : "r"(a[0]), "r"(a[1]), "r"(a[2]), "r"(a[3]), "r"(b[0]), "r"(b[1]));
}

// ------------------------- int8 GEMM -------------------------
// C[z][M,512] = sa[i]*sb[j]*(q1r1 + (q1r0+q0r1)/256), A digits [M,K], Bt digits [512,K].
// CTA tile 128x64, BK=64 int8 (64B SW64 rows), 8 warps of 32x32,
// 4-stage cp.async, one __syncthreads/iter, 2 CTAs/SM.
static constexpr int OFF_A1 = 0;
static constexpr int OFF_A0 = 8192;
static constexpr int OFF_B1 = 16384;
static constexpr int OFF_B0 = 20480;
static constexpr int STAGE_BYTES = 24576;
static constexpr int GEMM_SMEM   = 4 * STAGE_BYTES;   // 96 KB

DINL void ld_sec(uint32_t sdst, const char* src, int row0, size_t pitch,
                 size_t kbyte, int nIter, int tid)
{
    for (int i = 0; i < nIter; i++) {
        int idx = tid * 16 + i * 4096;
        int row = idx >> 6, col = idx & 63;
        uint32_t sw = (uint32_t)idx ^ (((uint32_t)idx >> 3) & 0x30);
        cp16(sdst + sw, src + (size_t)(row0 + row) * pitch + kbyte + col);
    }
}

template <bool FINAL>
__global__ void __launch_bounds__(256, 2)
i8gemm(const char* __restrict__ A1, const char* __restrict__ A0,
       const char* __restrict__ B1, const char* __restrict__ B0,
       const float* __restrict__ sa, const float* __restrict__ sb,
       float* __restrict__ C, int M, int K,
       const float* __restrict__ other, const float* __restrict__ bias)
{
    extern __shared__ char smem[];
    const uint32_t sb0 = smem_u32(smem);
    const int tid = threadIdx.x, wid = tid >> 5, lane = tid & 31;
    const int brow = blockIdx.y * 128, bcol = blockIdx.x * 64;
    const int warpM = (wid & 3) * 32, warpN = (wid >> 2) * 32;

    const int kchunks = K >> 6;                  // BK=64 int8
    const int Z = gridDim.z, z = blockIdx.z;
    const int kc0 = (int)(((long long)kchunks * z) / Z);
    const int kc1 = (int)(((long long)kchunks * (z + 1)) / Z);
    const int total = kc1 - kc0;

    const size_t pitch = (size_t)K;

    const uint32_t xorv = ((uint32_t)(lane >> 1) & 3) << 4;
    const uint32_t kaA = ((lane >> 4) & 1) * 16;
    const uint32_t kbB = ((lane >> 3) & 1) * 16;
    uint32_t aRowOff[2], bRowOff[2];
#pragma unroll
    for (int am = 0; am < 2; am++)
        aRowOff[am] = (uint32_t)(warpM + am * 16 + (lane & 15)) * 64;
#pragma unroll
    for (int bg = 0; bg < 2; bg++)
        bRowOff[bg] = (uint32_t)(warpN + bg * 16 + ((lane >> 4) & 1) * 8 + (lane & 7)) * 64;

    int acc1[2][4][4], accx[2][4][4];
#pragma unroll
    for (int i = 0; i < 2; i++)
#pragma unroll
        for (int j = 0; j < 4; j++)
#pragma unroll
            for (int t = 0; t < 4; t++) { acc1[i][j][t] = 0; accx[i][j][t] = 0; }

    // prologue: fill stages 0..2
#pragma unroll 1
    for (int p = 0; p < 3; p++) {
        if (p < total) {
            uint32_t sbb = sb0 + p * STAGE_BYTES;
            size_t kb = (size_t)(kc0 + p) * 64;
            ld_sec(sbb + OFF_A1, A1, brow, pitch, kb, 2, tid);
            ld_sec(sbb + OFF_A0, A0, brow, pitch, kb, 2, tid);
            ld_sec(sbb + OFF_B1, B1, bcol, pitch, kb, 1, tid);
            ld_sec(sbb + OFF_B0, B0, bcol, pitch, kb, 1, tid);
        }
        cp_commit();
    }

#pragma unroll 1
    for (int it = 0; it < total; ++it) {
        const int s = it & 3;
        cp_wait2();
        __syncthreads();

        const int nx = it + 3;
        if (nx < total) {
            uint32_t sbb = sb0 + (nx & 3) * STAGE_BYTES;
            size_t kb = (size_t)(kc0 + nx) * 64;
            ld_sec(sbb + OFF_A1, A1, brow, pitch, kb, 2, tid);
            ld_sec(sbb + OFF_A0, A0, brow, pitch, kb, 2, tid);
            ld_sec(sbb + OFF_B1, B1, bcol, pitch, kb, 1, tid);
            ld_sec(sbb + OFF_B0, B0, bcol, pitch, kb, 1, tid);
        }
        cp_commit();

        const uint32_t sbb = sb0 + s * STAGE_BYTES;
#pragma unroll
        for (int ks = 0; ks < 2; ks++) {
            const uint32_t kA = ((uint32_t)(ks * 32) + kaA) ^ xorv;
            const uint32_t kB = ((uint32_t)(ks * 32) + kbB) ^ xorv;
            uint32_t a1[2][4], a0[2][4];
#pragma unroll
            for (int am = 0; am < 2; am++) {
                ldsm4(a1[am], sbb + OFF_A1 + aRowOff[am] + kA);
                ldsm4(a0[am], sbb + OFF_A0 + aRowOff[am] + kA);
            }
#pragma unroll
            for (int bg = 0; bg < 2; bg++) {
                uint32_t b1[4], b0[4];
                ldsm4(b1, sbb + OFF_B1 + bRowOff[bg] + kB);
                ldsm4(b0, sbb + OFF_B0 + bRowOff[bg] + kB);
#pragma unroll
                for (int am = 0; am < 2; am++)
#pragma unroll
                    for (int h = 0; h < 2; h++)
                        mma_s8(acc1[am][bg * 2 + h], a1[am], b1 + h * 2);
#pragma unroll
                for (int am = 0; am < 2; am++)
#pragma unroll
                    for (int h = 0; h < 2; h++)
                        mma_s8(accx[am][bg * 2 + h], a1[am], b0 + h * 2);
#pragma unroll
                for (int am = 0; am < 2; am++)
#pragma unroll
                    for (int h = 0; h < 2; h++)
                        mma_s8(accx[am][bg * 2 + h], a0[am], b1 + h * 2);
            }
        }
    }

    // epilogue: dequantize
    float* Cz = C + (size_t)z * M * 512;
#pragma unroll
    for (int am = 0; am < 2; am++) {
#pragma unroll
        for (int bn = 0; bn < 4; bn++) {
            const int r0 = brow + warpM + am * 16 + (lane >> 2);
            const int cg = bcol + warpN + bn * 8 + (lane & 3) * 2;
            const float2 sbv = *(const float2*)(sb + cg);
#pragma unroll
            for (int h = 0; h < 2; h++) {
                const int row = r0 + h * 8;
                const float sav = sa[row];
                float2 v;
                v.x = sav * sbv.x * ((float)acc1[am][bn][h*2]   + (float)accx[am][bn][h*2]   * 0.00390625f);
                v.y = sav * sbv.y * ((float)acc1[am][bn][h*2+1] + (float)accx[am][bn][h*2+1] * 0.00390625f);
                size_t o = (size_t)row * 512 + cg;
                if (FINAL) {
                    float2 ov = *(const float2*)(other + o);
                    float2 bb = *(const float2*)(bias + cg);
                    v.x = fmaxf(fmaxf(v.x, ov.x) + bb.x, 0.0f);
                    v.y = fmaxf(fmaxf(v.y, ov.y) + bb.y, 0.0f);
                }
                *(float2*)(Cz + o) = v;
            }
        }
    }
}

// --------------- quantize A rows: v = sa*(q1 + q0/256) ---------------
DINL uint32_t pack4(int a, int b, int c, int d) {
    return (uint32_t)(a & 255) | ((uint32_t)(b & 255) << 8) |
           ((uint32_t)(c & 255) << 16) | ((uint32_t)(d & 255) << 24);
}
DINL void q2(float t, int& i1, int& i0) {
    i1 = __float2int_rn(t);
    i1 = max(-127, min(127, i1));
    float r = t - (float)i1;
    i0 = __float2int_rn(r * 256.0f);
    i0 = max(-127, min(127, i0));
}

__global__ void quantA(const float* __restrict__ src, char* __restrict__ q1,
                       char* __restrict__ q0, float* __restrict__ sa, int K)
{
    const int row = blockIdx.x * 8 + (threadIdx.x >> 5);
    const int lane = threadIdx.x & 31;
    const float* r = src + (size_t)row * K;
    float mx = 0.0f;
    for (int k = lane * 4; k < K; k += 128) {
        float4 v = *(const float4*)(r + k);
        mx = fmaxf(mx, fmaxf(fmaxf(fabsf(v.x), fabsf(v.y)), fmaxf(fabsf(v.z), fabsf(v.w))));
    }
#pragma unroll
    for (int o = 16; o; o >>= 1) mx = fmaxf(mx, __shfl_xor_sync(0xFFFFFFFFu, mx, o));
    const float inv = mx > 0.0f ? 127.0f / mx : 0.0f;
    if (lane == 0) sa[row] = mx / 127.0f;
    for (int k = lane * 4; k < K; k += 128) {
        float4 v = *(const float4*)(r + k);
        int a1, a0, b1, b0, c1, c0, d1, d0;
        q2(v.x * inv, a1, a0); q2(v.y * inv, b1, b0);
        q2(v.z * inv, c1, c0); q2(v.w * inv, d1, d0);
        *(uint32_t*)(q1 + (size_t)row * K + k) = pack4(a1, b1, c1, d1);
        *(uint32_t*)(q0 + (size_t)row * K + k) = pack4(a0, b0, c0, d0);
    }
}

// --------------- zero the colmax buffers (graph-replayable) ---------------
__global__ void zinit(float* a, float* b, float* c, float* d) {
    int i = threadIdx.x;
    a[i] = 0.0f; b[i] = 0.0f; c[i] = 0.0f; d[i] = 0.0f;
}

// --------------- column max of combined split-K partials ---------------
__global__ void colmax(const float* __restrict__ parts, int Z, int Min,
                       float* __restrict__ cmax)
{
    const int n = threadIdx.x;            // 512 threads
    const int m0 = blockIdx.x * 128;
    float mx = 0.0f;
    for (int m = m0; m < m0 + 128; m++) {
        float v = 0.0f;
        for (int zz = 0; zz < Z; zz++)
            v += parts[((size_t)zz * Min + m) * 512 + n];
        mx = fmaxf(mx, fabsf(v));
    }
    atomicMax((unsigned int*)(cmax + n), __float_as_uint(mx));
}

// --------------- combine + transpose + quantize (B operands) ---------------
__global__ void tq(const float* __restrict__ parts, int Z, int Min,
                   const float* __restrict__ cmax,
                   char* __restrict__ q1t, char* __restrict__ q0t,
                   float* __restrict__ sb,
                   const float* __restrict__ alpha, int aidx)
{
    __shared__ float tile[32][33];
    const int m0 = blockIdx.x * 32, n0 = blockIdx.y * 32;
    const int tx = threadIdx.x, ty = threadIdx.y;   // 32 x 8
    float ascale = 1.0f;
    if (aidx >= 0) {
        float e0 = __expf(alpha[0]), e1 = __expf(alpha[1]);
        ascale = (aidx == 0 ? e0 : e1) / (e0 + e1);
    }
#pragma unroll
    for (int j = 0; j < 32; j += 8) {
        int m = m0 + ty + j;
        float acc = 0.0f;
        for (int zz = 0; zz < Z; zz++)
            acc += parts[((size_t)zz * Min + m) * 512 + n0 + tx];
        tile[ty + j][tx] = acc;
    }
    __syncthreads();
#pragma unroll
    for (int j = 0; j < 32; j += 8) {
        const int n = n0 + ty + j;
        const float cm = cmax[n];
        const float cq = cm > 0.0f ? 127.0f / cm : 0.0f;
        float v = tile[tx][ty + j] * cq;
        int i1, i0;
        q2(v, i1, i0);
        size_t o = (size_t)n * Min + m0 + tx;
        q1t[o] = (char)i1;
        q0t[o] = (char)i0;
        if (blockIdx.x == 0 && tx == 0)
            sb[n] = ascale * cm / 127.0f;
    }
}

// ------------------------- host -------------------------
extern "C" void kernel_launch(void* const* d_in, const int* in_sizes, int n_in,
                              void* d_out, int out_size)
{
    const float* x     = (const float*)d_in[0];
    const float* w     = (const float*)d_in[1];
    const float* alpha = (const float*)d_in[2];
    const float* bias  = (const float*)d_in[3];
    const float* s0    = (const float*)d_in[4];
    const float* s1    = (const float*)d_in[5];
    const float* s2    = (const float*)d_in[6];
    const float* s3    = (const float*)d_in[7];
    float* out = (float*)d_out;

    char *xq1,*xq0,*s0q1,*s0q0,*s1q1,*s1q0,*s2q1,*s2q0,*s3q1,*s3q0;
    char *Wt1,*Wt0,*Pt1,*Pt0,*T1t1,*T1t0,*T3t1,*T3t0;
    float *pP,*pT1p,*pT3p,*pOL;
    float *sax,*sas0,*sas1,*sas2,*sas3,*sbW,*sbP,*sbT1,*sbT3,*cmW,*cmP,*cmT1,*cmT3;
    cudaGetSymbolAddress((void**)&xq1,  g_xq1);  cudaGetSymbolAddress((void**)&xq0,  g_xq0);
    cudaGetSymbolAddress((void**)&s0q1, g_s0q1); cudaGetSymbolAddress((void**)&s0q0, g_s0q0);
    cudaGetSymbolAddress((void**)&s1q1, g_s1q1); cudaGetSymbolAddress((void**)&s1q0, g_s1q0);
    cudaGetSymbolAddress((void**)&s2q1, g_s2q1); cudaGetSymbolAddress((void**)&s2q0, g_s2q0);
    cudaGetSymbolAddress((void**)&s3q1, g_s3q1); cudaGetSymbolAddress((void**)&s3q0, g_s3q0);
    cudaGetSymbolAddress((void**)&Wt1,  g_Wt1);  cudaGetSymbolAddress((void**)&Wt0,  g_Wt0);
    cudaGetSymbolAddress((void**)&Pt1,  g_Pt1);  cudaGetSymbolAddress((void**)&Pt0,  g_Pt0);
    cudaGetSymbolAddress((void**)&T1t1, g_T1t1); cudaGetSymbolAddress((void**)&T1t0, g_T1t0);
    cudaGetSymbolAddress((void**)&T3t1, g_T3t1); cudaGetSymbolAddress((void**)&T3t0, g_T3t0);
    cudaGetSymbolAddress((void**)&pP,   g_P);    cudaGetSymbolAddress((void**)&pT1p, g_T1p);
    cudaGetSymbolAddress((void**)&pT3p, g_T3p);  cudaGetSymbolAddress((void**)&pOL,  g_OL);
    cudaGetSymbolAddress((void**)&sax,  g_sax);  cudaGetSymbolAddress((void**)&sas0, g_sas0);
    cudaGetSymbolAddress((void**)&sas1, g_sas1); cudaGetSymbolAddress((void**)&sas2, g_sas2);
    cudaGetSymbolAddress((void**)&sas3, g_sas3);
    cudaGetSymbolAddress((void**)&sbW,  g_sbW);  cudaGetSymbolAddress((void**)&sbP,  g_sbP);
    cudaGetSymbolAddress((void**)&sbT1, g_sbT1); cudaGetSymbolAddress((void**)&sbT3, g_sbT3);
    cudaGetSymbolAddress((void**)&cmW,  g_cmW);  cudaGetSymbolAddress((void**)&cmP,  g_cmP);
    cudaGetSymbolAddress((void**)&cmT1, g_cmT1); cudaGetSymbolAddress((void**)&cmT3, g_cmT3);

    cudaFuncSetAttribute(i8gemm<false>, cudaFuncAttributeMaxDynamicSharedMemorySize, GEMM_SMEM);
    cudaFuncSetAttribute(i8gemm<true>,  cudaFuncAttributeMaxDynamicSharedMemorySize, GEMM_SMEM);

    // ---- pipeline ----
    quantA<<<NN / 8, 256>>>(x,  xq1,  xq0,  sax,  DD);                                     // 1
    quantA<<<NH / 8, 256>>>(s3, s3q1, s3q0, sas3, NN);                                     // 2
    zinit<<<1, DD>>>(cmW, cmP, cmT1, cmT3);                                                // 3
    colmax<<<DD / 128, DD>>>(w, 1, DD, cmW);                                               // 4
    tq<<<dim3(DD / 32, 16), dim3(32, 8)>>>(w, 1, DD, cmW, Wt1, Wt0, sbW, alpha, -1);       // 5
    // G1: P = x @ W   [8192,512], K=512
    i8gemm<false><<<dim3(8, 64, 1), 256, GEMM_SMEM>>>(xq1, xq0, Wt1, Wt0, sax, sbW,        // 6
                                                      pP, NN, DD, nullptr, nullptr);
    colmax<<<NN / 128, DD>>>(pP, 1, NN, cmP);                                              // 7
    tq<<<dim3(NN / 32, 16), dim3(32, 8)>>>(pP, 1, NN, cmP, Pt1, Pt0, sbP, alpha, -1);      // 8
    // G4: T3 = s3 @ P   [6144,512], K=8192, split-K=3
    i8gemm<false><<<dim3(8, 48, 3), 256, GEMM_SMEM>>>(s3q1, s3q0, Pt1, Pt0, sas3, sbP,     // 9
                                                      pT3p, NH, NN, nullptr, nullptr);
    quantA<<<KK / 8, 256>>>(s1, s1q1, s1q0, sas1, NN);                                     // 10
    // G2: T1 = s1 @ P   [2048,512], K=8192, split-K=4
    i8gemm<false><<<dim3(8, 16, 4), 256, GEMM_SMEM>>>(s1q1, s1q0, Pt1, Pt0, sas1, sbP,     // 11
                                                      pT1p, KK, NN, nullptr, nullptr);
    colmax<<<KK / 128, DD>>>(pT1p, 4, KK, cmT1);                                           // 12
    tq<<<dim3(KK / 32, 16), dim3(32, 8)>>>(pT1p, 4, KK, cmT1, T1t1, T1t0, sbT1, alpha, 0); // 13
    quantA<<<NN / 8, 256>>>(s0, s0q1, s0q0, sas0, KK);                                     // 14
    // G3: OL = s0 @ T1   [8192,512], K=2048
    i8gemm<false><<<dim3(8, 64, 1), 256, GEMM_SMEM>>>(s0q1, s0q0, T1t1, T1t0, sas0, sbT1,  // 15
                                                      pOL, NN, KK, nullptr, nullptr);
    colmax<<<NH / 128, DD>>>(pT3p, 3, NH, cmT3);                                           // 16
    tq<<<dim3(NH / 32, 16), dim3(32, 8)>>>(pT3p, 3, NH, cmT3, T3t1, T3t0, sbT3, alpha, 1); // 17
    quantA<<<NN / 8, 256>>>(s2, s2q1, s2q0, sas2, NH);                                     // 18
    // G5: out = relu(max(OL, s2 @ T3) + bias)   [8192,512], K=6144
    i8gemm<true><<<dim3(8, 64, 1), 256, GEMM_SMEM>>>(s2q1, s2q0, T3t1, T3t0, sas2, sbT3,   // 19
                                                     out, NN, NH, pOL, bias);
}

// round 8
// speedup vs baseline: 3.0808x; 3.0808x over previous
#include <cuda_runtime.h>
#include <cuda_bf16.h>
#include <cstdint>
#include <cstddef>

#define DINL __device__ __forceinline__

// ------------------------- problem sizes -------------------------
#define NN 8192
#define KK 2048
#define DD 512
#define NH (NN - KK)   // 6144

// ------------------------- scratch (static device globals) -------------------------
__device__ __nv_bfloat16 g_xh[NN*DD],  g_xl[NN*DD];
__device__ __nv_bfloat16 g_s0h[NN*KK], g_s0l[NN*KK];
__device__ __nv_bfloat16 g_s1h[KK*NN], g_s1l[KK*NN];
__device__ __nv_bfloat16 g_s2h[(size_t)NN*NH], g_s2l[(size_t)NN*NH];
__device__ __nv_bfloat16 g_s3h[(size_t)NH*NN], g_s3l[(size_t)NH*NN];
__device__ __nv_bfloat16 g_Wth[DD*DD],  g_Wtl[DD*DD];
__device__ __nv_bfloat16 g_Pth[DD*NN],  g_Ptl[DD*NN];
__device__ __nv_bfloat16 g_T1h[DD*KK],  g_T1l[DD*KK];
__device__ __nv_bfloat16 g_T3h[DD*NH],  g_T3l[DD*NH];
__device__ float g_P  [NN*DD];
__device__ float g_T1p[4*KK*DD];
__device__ float g_T3p[3*NH*DD];
__device__ float g_OL [NN*DD];

// ------------------------- ptx helpers (base ISA only) ----
DINL uint32_t smem_u32(const void* p) {
    uint32_t a;
    asm("{ .reg .u64 t; cvta.to.shared.u64 t, %1; cvt.u32.u64 %0, t; }" : "=r"(a) : "l"(p));
    return a;
}
DINL void cp16(uint32_t saddr, const void* g) {
    asm volatile("cp.async.cg.shared.global [%0], [%1], 16;" :: "r"(saddr), "l"(g));
}
DINL void cp_commit() { asm volatile("cp.async.commit_group;" ::: "memory"); }
DINL void cp_wait1()  { asm volatile("cp.async.wait_group 1;" ::: "memory"); }
DINL void cp_wait0()  { asm volatile("cp.async.wait_group 0;" ::: "memory"); }

DINL void ldsm4(uint32_t (&r)[4], uint32_t addr) {
    asm volatile("ldmatrix.sync.aligned.m8n8.x4.shared.b16 {%0,%1,%2,%3}, [%4];"
                 : "=r"(r[0]), "=r"(r[1]), "=r"(r[2]), "=r"(r[3]) : "r"(addr));
}
DINL void mma_bf16(float (&d)[4], const uint32_t (&a)[4], const uint32_t* b) {
    asm volatile(
        "mma.sync.aligned.m16n8k16.row.col.f32.bf16.bf16.f32 "
        "{%0,%1,%2,%3}, {%4,%5,%6,%7}, {%8,%9}, {%0,%1,%2,%3};"
        : "+f"(d[0]), "+f"(d[1]), "+f"(d[2]), "+f"(d[3])
        : "r"(a[0]), "r"(a[1]), "r"(a[2]), "r"(a[3]), "r"(b[0]), "r"(b[1]));
}

// ------------------------- GEMM -------------------------
// C[z][M,512] = A[M,K] @ Bt^T with bf16 hi/lo pairs (bf16x3 scheme).
// CTA tile 256x128, BK=64 (128B SW128 rows), 8 warps of 64x64, 2-stage cp.async.
// B fragments double-buffered: ldsm for bg+1 issued before bg's MMA block.
static constexpr int OFF_AH = 0;
static constexpr int OFF_AL = 32768;
static constexpr int OFF_BH = 65536;
static constexpr int OFF_BL = 81920;
static constexpr int STAGE_BYTES = 98304;
static constexpr int GEMM_SMEM   = 2 * STAGE_BYTES;   // 192 KB

DINL void ld_sec(uint32_t sdst, const char* src, int row0, size_t pitch,
                 size_t kbyte, int nIter, int tid)
{
    for (int i = 0; i < nIter; i++) {
        int idx = tid * 16 + i * 4096;
        int row = idx >> 7, col = idx & 127;
        uint32_t sw = (uint32_t)idx ^ (((uint32_t)idx >> 3) & 0x70);
        cp16(sdst + sw, src + (size_t)(row0 + row) * pitch + kbyte + col);
    }
}

template <bool FINAL>
__global__ void __launch_bounds__(256, 1)
bfgemm(const __nv_bfloat16* __restrict__ Ah_, const __nv_bfloat16* __restrict__ Al_,
       const __nv_bfloat16* __restrict__ Bh_, const __nv_bfloat16* __restrict__ Bl_,
       float* __restrict__ C, int M, int K,
       const float* __restrict__ other, const float* __restrict__ bias)
{
    extern __shared__ char smem[];
    const uint32_t sb0 = smem_u32(smem);
    const int tid = threadIdx.x, wid = tid >> 5, lane = tid & 31;
    const int brow = blockIdx.y * 256, bcol = blockIdx.x * 128;
    const int warpM = (wid & 3) * 64, warpN = (wid >> 2) * 64;

    const int kchunks = K >> 6;
    const int Z = gridDim.z, z = blockIdx.z;
    const int kc0 = (int)(((long long)kchunks * z) / Z);
    const int kc1 = (int)(((long long)kchunks * (z + 1)) / Z);
    const int total = kc1 - kc0;
    float* Cz = C + (size_t)z * M * 512;

    const char* Ah = (const char*)Ah_;
    const char* Al = (const char*)Al_;
    const char* Bh = (const char*)Bh_;
    const char* Bl = (const char*)Bl_;
    const size_t pitch = (size_t)K * 2;

    const uint32_t xorv = (uint32_t)(lane & 7) << 4;
    const uint32_t kaA = ((lane >> 4) & 1) * 16;
    const uint32_t kbB = ((lane >> 3) & 1) * 16;
    uint32_t aRowOff[4], bRowOff[4];
#pragma unroll
    for (int am = 0; am < 4; am++)
        aRowOff[am] = (uint32_t)(warpM + am * 16 + (lane & 15)) * 128;
#pragma unroll
    for (int bg = 0; bg < 4; bg++)
        bRowOff[bg] = (uint32_t)(warpN + bg * 16 + ((lane >> 4) & 1) * 8 + (lane & 7)) * 128;

    float acc[4][8][4];
#pragma unroll
    for (int i = 0; i < 4; i++)
#pragma unroll
        for (int j = 0; j < 8; j++)
#pragma unroll
            for (int t = 0; t < 4; t++) acc[i][j][t] = 0.0f;

    // pipeline prologue: fill both stages
#pragma unroll 1
    for (int p = 0; p < 2; p++) {
        uint32_t sb = sb0 + p * STAGE_BYTES;
        size_t kb = (size_t)(kc0 + p) * 128;
        ld_sec(sb + OFF_AH, Ah, brow, pitch, kb, 8, tid);
        ld_sec(sb + OFF_AL, Al, brow, pitch, kb, 8, tid);
        ld_sec(sb + OFF_BH, Bh, bcol, pitch, kb, 4, tid);
        ld_sec(sb + OFF_BL, Bl, bcol, pitch, kb, 4, tid);
        cp_commit();
    }

#pragma unroll 1
    for (int it = 0; it < total; ++it) {
        const int s = it & 1;
        if (it < total - 1) cp_wait1(); else cp_wait0();
        __syncthreads();

        const uint32_t sb = sb0 + s * STAGE_BYTES;
#pragma unroll 1
        for (int ks = 0; ks < 4; ks++) {
            const uint32_t kA = ((uint32_t)(ks * 32) + kaA) ^ xorv;
            const uint32_t kB = ((uint32_t)(ks * 32) + kbB) ^ xorv;
            uint32_t ah[4][4], al[4][4];
#pragma unroll
            for (int am = 0; am < 4; am++) {
                ldsm4(ah[am], sb + OFF_AH + aRowOff[am] + kA);
                ldsm4(al[am], sb + OFF_AL + aRowOff[am] + kA);
            }
            // B fragment double buffer: prefetch bg+1 before bg's MMAs
            uint32_t bh[2][4], bl[2][4];
            ldsm4(bh[0], sb + OFF_BH + bRowOff[0] + kB);
            ldsm4(bl[0], sb + OFF_BL + bRowOff[0] + kB);
#pragma unroll
            for (int bg = 0; bg < 4; bg++) {
                const int cur = bg & 1;
                if (bg < 3) {
                    ldsm4(bh[cur ^ 1], sb + OFF_BH + bRowOff[bg + 1] + kB);
                    ldsm4(bl[cur ^ 1], sb + OFF_BL + bRowOff[bg + 1] + kB);
                }
#pragma unroll
                for (int am = 0; am < 4; am++)
#pragma unroll
                    for (int h = 0; h < 2; h++)
                        mma_bf16(acc[am][bg * 2 + h], ah[am], bh[cur] + h * 2);
#pragma unroll
                for (int am = 0; am < 4; am++)
#pragma unroll
                    for (int h = 0; h < 2; h++)
                        mma_bf16(acc[am][bg * 2 + h], ah[am], bl[cur] + h * 2);
#pragma unroll
                for (int am = 0; am < 4; am++)
#pragma unroll
                    for (int h = 0; h < 2; h++)
                        mma_bf16(acc[am][bg * 2 + h], al[am], bh[cur] + h * 2);
            }
        }
        __syncthreads();
        const int nx = it + 2;
        if (nx < total) {
            size_t kb = (size_t)(kc0 + nx) * 128;
            ld_sec(sb + OFF_AH, Ah, brow, pitch, kb, 8, tid);
            ld_sec(sb + OFF_AL, Al, brow, pitch, kb, 8, tid);
            ld_sec(sb + OFF_BH, Bh, bcol, pitch, kb, 4, tid);
            ld_sec(sb + OFF_BL, Bl, bcol, pitch, kb, 4, tid);
            cp_commit();
        }
    }

    // epilogue
#pragma unroll
    for (int am = 0; am < 4; am++) {
#pragma unroll
        for (int bn = 0; bn < 8; bn++) {
            const int r0 = brow + warpM + am * 16 + (lane >> 2);
            const int cg = bcol + warpN + bn * 8 + (lane & 3) * 2;
#pragma unroll
            for (int h = 0; h < 2; h++) {
                const int row = r0 + h * 8;
                float2 v = make_float2(acc[am][bn][h * 2], acc[am][bn][h * 2 + 1]);
                size_t o = (size_t)row * 512 + cg;
                if (FINAL) {
                    float2 ov = *(const float2*)(other + o);
                    float2 bb = *(const float2*)(bias + cg);
                    v.x = fmaxf(fmaxf(v.x, ov.x) + bb.x, 0.0f);
                    v.y = fmaxf(fmaxf(v.y, ov.y) + bb.y, 0.0f);
                }
                *(float2*)(Cz + o) = v;
            }
        }
    }
}

// ------------------------- split fp32 -> bf16 hi/lo -------------------------
__global__ void splitk(const float* __restrict__ src, __nv_bfloat16* __restrict__ h,
                       __nv_bfloat16* __restrict__ l, size_t n4)
{
    size_t stride = (size_t)gridDim.x * blockDim.x;
    for (size_t i = (size_t)blockIdx.x * blockDim.x + threadIdx.x; i < n4; i += stride) {
        float4 v = ((const float4*)src)[i];
        __nv_bfloat16 h0 = __float2bfloat16(v.x), h1 = __float2bfloat16(v.y);
        __nv_bfloat16 h2 = __float2bfloat16(v.z), h3 = __float2bfloat16(v.w);
        __nv_bfloat16 l0 = __float2bfloat16(v.x - __bfloat162float(h0));
        __nv_bfloat16 l1 = __float2bfloat16(v.y - __bfloat162float(h1));
        __nv_bfloat16 l2 = __float2bfloat16(v.z - __bfloat162float(h2));
        __nv_bfloat16 l3 = __float2bfloat16(v.w - __bfloat162float(h3));
        uint2 hp, lp;
        hp.x = (uint32_t)__bfloat16_as_ushort(h0) | ((uint32_t)__bfloat16_as_ushort(h1) << 16);
        hp.y = (uint32_t)__bfloat16_as_ushort(h2) | ((uint32_t)__bfloat16_as_ushort(h3) << 16);
        lp.x = (uint32_t)__bfloat16_as_ushort(l0) | ((uint32_t)__bfloat16_as_ushort(l1) << 16);
        lp.y = (uint32_t)__bfloat16_as_ushort(l2) | ((uint32_t)__bfloat16_as_ushort(l3) << 16);
        ((uint2*)h)[i] = hp;
        ((uint2*)l)[i] = lp;
    }
}

// ------------------- combine(split-K) + scale + transpose + split ----------
__global__ void cst(const float* __restrict__ parts, int Z, int Min,
                    __nv_bfloat16* __restrict__ th, __nv_bfloat16* __restrict__ tl,
                    const float* __restrict__ alpha, int aidx)
{
    __shared__ float tile[32][33];
    const int m0 = blockIdx.x * 32, n0 = blockIdx.y * 32;
    const int tx = threadIdx.x, ty = threadIdx.y;   // 32 x 8
    float s = 1.0f;
    if (aidx >= 0) {
        float e0 = __expf(alpha[0]), e1 = __expf(alpha[1]);
        s = (aidx == 0 ? e0 : e1) / (e0 + e1);
    }
#pragma unroll
    for (int j = 0; j < 32; j += 8) {
        int m = m0 + ty + j;
        float acc = 0.0f;
        for (int zz = 0; zz < Z; zz++)
            acc += parts[((size_t)zz * Min + m) * 512 + n0 + tx];
        tile[ty + j][tx] = acc * s;
    }
    __syncthreads();
#pragma unroll
    for (int j = 0; j < 32; j += 8) {
        float v = tile[tx][ty + j];
        __nv_bfloat16 h = __float2bfloat16(v);
        __nv_bfloat16 l = __float2bfloat16(v - __bfloat162float(h));
        size_t o = (size_t)(n0 + ty + j) * Min + m0 + tx;
        th[o] = h;
        tl[o] = l;
    }
}

// ------------------------- host -------------------------
extern "C" void kernel_launch(void* const* d_in, const int* in_sizes, int n_in,
                              void* d_out, int out_size)
{
    const float* x     = (const float*)d_in[0];
    const float* w     = (const float*)d_in[1];
    const float* alpha = (const float*)d_in[2];
    const float* bias  = (const float*)d_in[3];
    const float* s0    = (const float*)d_in[4];
    const float* s1    = (const float*)d_in[5];
    const float* s2    = (const float*)d_in[6];
    const float* s3    = (const float*)d_in[7];
    float* out = (float*)d_out;

    __nv_bfloat16 *xh, *xl, *s0h, *s0l, *s1h, *s1l, *s2h, *s2l, *s3h, *s3l;
    __nv_bfloat16 *Wth, *Wtl, *Pth, *Ptl, *T1h, *T1l, *T3h, *T3l;
    float *pP, *pT1p, *pT3p, *pOL;
    cudaGetSymbolAddress((void**)&xh,  g_xh);  cudaGetSymbolAddress((void**)&xl,  g_xl);
    cudaGetSymbolAddress((void**)&s0h, g_s0h); cudaGetSymbolAddress((void**)&s0l, g_s0l);
    cudaGetSymbolAddress((void**)&s1h, g_s1h); cudaGetSymbolAddress((void**)&s1l, g_s1l);
    cudaGetSymbolAddress((void**)&s2h, g_s2h); cudaGetSymbolAddress((void**)&s2l, g_s2l);
    cudaGetSymbolAddress((void**)&s3h, g_s3h); cudaGetSymbolAddress((void**)&s3l, g_s3l);
    cudaGetSymbolAddress((void**)&Wth, g_Wth); cudaGetSymbolAddress((void**)&Wtl, g_Wtl);
    cudaGetSymbolAddress((void**)&Pth, g_Pth); cudaGetSymbolAddress((void**)&Ptl, g_Ptl);
    cudaGetSymbolAddress((void**)&T1h, g_T1h); cudaGetSymbolAddress((void**)&T1l, g_T1l);
    cudaGetSymbolAddress((void**)&T3h, g_T3h); cudaGetSymbolAddress((void**)&T3l, g_T3l);
    cudaGetSymbolAddress((void**)&pP,  g_P);   cudaGetSymbolAddress((void**)&pT1p, g_T1p);
    cudaGetSymbolAddress((void**)&pT3p, g_T3p); cudaGetSymbolAddress((void**)&pOL, g_OL);

    cudaFuncSetAttribute(bfgemm<false>, cudaFuncAttributeMaxDynamicSharedMemorySize, GEMM_SMEM);
    cudaFuncSetAttribute(bfgemm<true>,  cudaFuncAttributeMaxDynamicSharedMemorySize, GEMM_SMEM);

    // Launch order: 4th launch (ncu capture) = G1.
    splitk<<<1024, 256>>>(x,  xh,  xl,  (size_t)NN * DD / 4);                            // 1
    cst<<<dim3(DD / 32, 16), dim3(32, 8)>>>(w, 1, DD, Wth, Wtl, alpha, -1);              // 2
    splitk<<<2048, 256>>>(s3, s3h, s3l, (size_t)NH * NN / 4);                            // 3
    // G1: P = x @ W        [8192,512], K=512                                  <- profiled
    bfgemm<false><<<dim3(4, 32, 1), 256, GEMM_SMEM>>>(xh, xl, Wth, Wtl, pP, NN, DD,      // 4
                                                      nullptr, nullptr);
    cst<<<dim3(NN / 32, 16), dim3(32, 8)>>>(pP, 1, NN, Pth, Ptl, alpha, -1);             // 5
    // G4: T3 = s3 @ P      [6144,512], K=8192, split-K=3
    bfgemm<false><<<dim3(4, 24, 3), 256, GEMM_SMEM>>>(s3h, s3l, Pth, Ptl, pT3p, NH, NN,  // 6
                                                      nullptr, nullptr);
    splitk<<<1024, 256>>>(s1, s1h, s1l, (size_t)KK * NN / 4);                            // 7
    // G2: T1 = s1 @ P      [2048,512], K=8192, split-K=4
    bfgemm<false><<<dim3(4, 8, 4), 256, GEMM_SMEM>>>(s1h, s1l, Pth, Ptl, pT1p, KK, NN,   // 8
                                                     nullptr, nullptr);
    cst<<<dim3(KK / 32, 16), dim3(32, 8)>>>(pT1p, 4, KK, T1h, T1l, alpha, 0);            // 9
    splitk<<<1024, 256>>>(s0, s0h, s0l, (size_t)NN * KK / 4);                            // 10
    // G3: OL = s0 @ T1     [8192,512], K=2048
    bfgemm<false><<<dim3(4, 32, 1), 256, GEMM_SMEM>>>(s0h, s0l, T1h, T1l, pOL, NN, KK,   // 11
                                                      nullptr, nullptr);
    cst<<<dim3(NH / 32, 16), dim3(32, 8)>>>(pT3p, 3, NH, T3h, T3l, alpha, 1);            // 12
    splitk<<<2048, 256>>>(s2, s2h, s2l, (size_t)NN * NH / 4);                            // 13
    // G5: out = relu(max(OL, s2 @ T3) + bias)   [8192,512], K=6144
    bfgemm<true><<<dim3(4, 32, 1), 256, GEMM_SMEM>>>(s2h, s2l, T3h, T3l, out, NN, NH,    // 14
                                                     pOL, bias);
}

// round 9
// speedup vs baseline: 4.3662x; 1.4172x over previous
#include <cuda_runtime.h>
#include <cuda_fp16.h>
#include <cstdint>
#include <cstddef>

#define DINL __device__ __forceinline__

// ------------------------- problem sizes -------------------------
#define NN 8192
#define KK 2048
#define DD 512
#define NH (NN - KK)   // 6144

// ------------------------- scratch (static device globals) -------------------------
__device__ __half g_xf [NN*DD];
__device__ __half g_s0f[NN*KK];
__device__ __half g_s1f[KK*NN];
__device__ __half g_s2f[(size_t)NN*NH];
__device__ __half g_s3f[(size_t)NH*NN];
__device__ __half g_Wth[DD*DD],  g_Wtl[DD*DD];
__device__ __half g_Pth[DD*NN],  g_Ptl[DD*NN];
__device__ __half g_T1h[DD*KK],  g_T1l[DD*KK];
__device__ __half g_T3h[DD*NH],  g_T3l[DD*NH];
__device__ float g_P  [NN*DD];
__device__ float g_T1p[4*KK*DD];
__device__ float g_T3p[3*NH*DD];
__device__ float g_OL [NN*DD];

// ------------------------- ptx helpers (base ISA only) ----
DINL uint32_t smem_u32(const void* p) {
    uint32_t a;
    asm("{ .reg .u64 t; cvta.to.shared.u64 t, %1; cvt.u32.u64 %0, t; }" : "=r"(a) : "l"(p));
    return a;
}
DINL void cp16(uint32_t saddr, const void* g) {
    asm volatile("cp.async.cg.shared.global [%0], [%1], 16;" :: "r"(saddr), "l"(g));
}
DINL void cp_commit() { asm volatile("cp.async.commit_group;" ::: "memory"); }
DINL void cp_wait1()  { asm volatile("cp.async.wait_group 1;" ::: "memory"); }
DINL void cp_wait0()  { asm volatile("cp.async.wait_group 0;" ::: "memory"); }

DINL void ldsm4(uint32_t (&r)[4], uint32_t addr) {
    asm volatile("ldmatrix.sync.aligned.m8n8.x4.shared.b16 {%0,%1,%2,%3}, [%4];"
                 : "=r"(r[0]), "=r"(r[1]), "=r"(r[2]), "=r"(r[3]) : "r"(addr));
}
DINL void mma_f16(float (&d)[4], const uint32_t (&a)[4], const uint32_t* b) {
    asm volatile(
        "mma.sync.aligned.m16n8k16.row.col.f32.f16.f16.f32 "
        "{%0,%1,%2,%3}, {%4,%5,%6,%7}, {%8,%9}, {%0,%1,%2,%3};"
        : "+f"(d[0]), "+f"(d[1]), "+f"(d[2]), "+f"(d[3])
        : "r"(a[0]), "r"(a[1]), "r"(a[2]), "r"(a[3]), "r"(b[0]), "r"(b[1]));
}

// ------------------------- GEMM -------------------------
// C[z][M,512] = A[M,K] @ Bt^T, A single fp16, Bt fp16 hi/lo (2-pass scheme).
// CTA tile 256x128, BK=64 (128B SW128 rows), 8 warps of 64x64, 2-stage cp.async.
static constexpr int OFF_A  = 0;       // 32 KB (256 rows x 128B)
static constexpr int OFF_BH = 32768;   // 16 KB
static constexpr int OFF_BL = 49152;   // 16 KB
static constexpr int STAGE_BYTES = 65536;
static constexpr int GEMM_SMEM   = 2 * STAGE_BYTES;   // 128 KB

DINL void ld_sec(uint32_t sdst, const char* src, int row0, size_t pitch,
                 size_t kbyte, int nIter, int tid)
{
    for (int i = 0; i < nIter; i++) {
        int idx = tid * 16 + i * 4096;
        int row = idx >> 7, col = idx & 127;
        uint32_t sw = (uint32_t)idx ^ (((uint32_t)idx >> 3) & 0x70);
        cp16(sdst + sw, src + (size_t)(row0 + row) * pitch + kbyte + col);
    }
}

template <bool FINAL>
__global__ void __launch_bounds__(256, 1)
hgemm(const __half* __restrict__ A_,
      const __half* __restrict__ Bh_, const __half* __restrict__ Bl_,
      float* __restrict__ C, int M, int K,
      const float* __restrict__ other, const float* __restrict__ bias)
{
    extern __shared__ char smem[];
    const uint32_t sb0 = smem_u32(smem);
    const int tid = threadIdx.x, wid = tid >> 5, lane = tid & 31;
    const int brow = blockIdx.y * 256, bcol = blockIdx.x * 128;
    const int warpM = (wid & 3) * 64, warpN = (wid >> 2) * 64;

    const int kchunks = K >> 6;
    const int Z = gridDim.z, z = blockIdx.z;
    const int kc0 = (int)(((long long)kchunks * z) / Z);
    const int kc1 = (int)(((long long)kchunks * (z + 1)) / Z);
    const int total = kc1 - kc0;
    float* Cz = C + (size_t)z * M * 512;

    const char* A  = (const char*)A_;
    const char* Bh = (const char*)Bh_;
    const char* Bl = (const char*)Bl_;
    const size_t pitch = (size_t)K * 2;

    const uint32_t xorv = (uint32_t)(lane & 7) << 4;
    const uint32_t kaA = ((lane >> 4) & 1) * 16;
    const uint32_t kbB = ((lane >> 3) & 1) * 16;
    uint32_t aRowOff[4], bRowOff[4];
#pragma unroll
    for (int am = 0; am < 4; am++)
        aRowOff[am] = (uint32_t)(warpM + am * 16 + (lane & 15)) * 128;
#pragma unroll
    for (int bg = 0; bg < 4; bg++)
        bRowOff[bg] = (uint32_t)(warpN + bg * 16 + ((lane >> 4) & 1) * 8 + (lane & 7)) * 128;

    float acc[4][8][4];
#pragma unroll
    for (int i = 0; i < 4; i++)
#pragma unroll
        for (int j = 0; j < 8; j++)
#pragma unroll
            for (int t = 0; t < 4; t++) acc[i][j][t] = 0.0f;

    // pipeline prologue: fill both stages
#pragma unroll 1
    for (int p = 0; p < 2; p++) {
        uint32_t sb = sb0 + p * STAGE_BYTES;
        size_t kb = (size_t)(kc0 + p) * 128;
        ld_sec(sb + OFF_A,  A,  brow, pitch, kb, 8, tid);
        ld_sec(sb + OFF_BH, Bh, bcol, pitch, kb, 4, tid);
        ld_sec(sb + OFF_BL, Bl, bcol, pitch, kb, 4, tid);
        cp_commit();
    }

#pragma unroll 1
    for (int it = 0; it < total; ++it) {
        const int s = it & 1;
        if (it < total - 1) cp_wait1(); else cp_wait0();
        __syncthreads();

        const uint32_t sb = sb0 + s * STAGE_BYTES;
#pragma unroll 1
        for (int ks = 0; ks < 4; ks++) {
            const uint32_t kA = ((uint32_t)(ks * 32) + kaA) ^ xorv;
            const uint32_t kB = ((uint32_t)(ks * 32) + kbB) ^ xorv;
            uint32_t ah[4][4];
#pragma unroll
            for (int am = 0; am < 4; am++)
                ldsm4(ah[am], sb + OFF_A + aRowOff[am] + kA);
#pragma unroll
            for (int bg = 0; bg < 4; bg++) {
                uint32_t bh[4], bl[4];
                ldsm4(bh, sb + OFF_BH + bRowOff[bg] + kB);
                ldsm4(bl, sb + OFF_BL + bRowOff[bg] + kB);
#pragma unroll
                for (int am = 0; am < 4; am++)
#pragma unroll
                    for (int h = 0; h < 2; h++)
                        mma_f16(acc[am][bg * 2 + h], ah[am], bh + h * 2);
#pragma unroll
                for (int am = 0; am < 4; am++)
#pragma unroll
                    for (int h = 0; h < 2; h++)
                        mma_f16(acc[am][bg * 2 + h], ah[am], bl + h * 2);
            }
        }
        __syncthreads();
        const int nx = it + 2;
        if (nx < total) {
            size_t kb = (size_t)(kc0 + nx) * 128;
            ld_sec(sb + OFF_A,  A,  brow, pitch, kb, 8, tid);
            ld_sec(sb + OFF_BH, Bh, bcol, pitch, kb, 4, tid);
            ld_sec(sb + OFF_BL, Bl, bcol, pitch, kb, 4, tid);
            cp_commit();
        }
    }

    // epilogue
#pragma unroll
    for (int am = 0; am < 4; am++) {
#pragma unroll
        for (int bn = 0; bn < 8; bn++) {
            const int r0 = brow + warpM + am * 16 + (lane >> 2);
            const int cg = bcol + warpN + bn * 8 + (lane & 3) * 2;
#pragma unroll
            for (int h = 0; h < 2; h++) {
                const int row = r0 + h * 8;
                float2 v = make_float2(acc[am][bn][h * 2], acc[am][bn][h * 2 + 1]);
                size_t o = (size_t)row * 512 + cg;
                if (FINAL) {
                    float2 ov = *(const float2*)(other + o);
                    float2 bb = *(const float2*)(bias + cg);
                    v.x = fmaxf(fmaxf(v.x, ov.x) + bb.x, 0.0f);
                    v.y = fmaxf(fmaxf(v.y, ov.y) + bb.y, 0.0f);
                }
                *(float2*)(Cz + o) = v;
            }
        }
    }
}

// ------------------------- convert fp32 -> fp16 (A operands) -------------------------
__global__ void cvtA(const float* __restrict__ src, __half* __restrict__ dst, size_t n4)
{
    size_t stride = (size_t)gridDim.x * blockDim.x;
    for (size_t i = (size_t)blockIdx.x * blockDim.x + threadIdx.x; i < n4; i += stride) {
        float4 v = ((const float4*)src)[i];
        __half2 p0 = __floats2half2_rn(v.x, v.y);
        __half2 p1 = __floats2half2_rn(v.z, v.w);
        uint2 o;
        o.x = *(const uint32_t*)&p0;
        o.y = *(const uint32_t*)&p1;
        ((uint2*)dst)[i] = o;
    }
}

// ------------- combine(split-K) + scale + transpose + fp16 hi/lo split -------------
// in: parts [Z, Min, 512] fp32. out: th/tl [512, Min] fp16, scaled by softmax(alpha)[aidx].
__global__ void cst(const float* __restrict__ parts, int Z, int Min,
                    __half* __restrict__ th, __half* __restrict__ tl,
                    const float* __restrict__ alpha, int aidx)
{
    __shared__ float tile[32][33];
    const int m0 = blockIdx.x * 32, n0 = blockIdx.y * 32;
    const int tx = threadIdx.x, ty = threadIdx.y;   // 32 x 8
    float s = 1.0f;
    if (aidx >= 0) {
        float e0 = __expf(alpha[0]), e1 = __expf(alpha[1]);
        s = (aidx == 0 ? e0 : e1) / (e0 + e1);
    }
#pragma unroll
    for (int j = 0; j < 32; j += 8) {
        int m = m0 + ty + j;
        float acc = 0.0f;
        for (int zz = 0; zz < Z; zz++)
            acc += parts[((size_t)zz * Min + m) * 512 + n0 + tx];
        tile[ty + j][tx] = acc * s;
    }
    __syncthreads();
#pragma unroll
    for (int j = 0; j < 32; j += 8) {
        float v = tile[tx][ty + j];
        __half h = __float2half_rn(v);
        __half l = __float2half_rn(v - __half2float(h));
        size_t o = (size_t)(n0 + ty + j) * Min + m0 + tx;
        th[o] = h;
        tl[o] = l;
    }
}

// ------------------------- host -------------------------
extern "C" void kernel_launch(void* const* d_in, const int* in_sizes, int n_in,
                              void* d_out, int out_size)
{
    const float* x     = (const float*)d_in[0];
    const float* w     = (const float*)d_in[1];
    const float* alpha = (const float*)d_in[2];
    const float* bias  = (const float*)d_in[3];
    const float* s0    = (const float*)d_in[4];
    const float* s1    = (const float*)d_in[5];
    const float* s2    = (const float*)d_in[6];
    const float* s3    = (const float*)d_in[7];
    float* out = (float*)d_out;

    __half *xf, *s0f, *s1f, *s2f, *s3f;
    __half *Wth, *Wtl, *Pth, *Ptl, *T1h, *T1l, *T3h, *T3l;
    float *pP, *pT1p, *pT3p, *pOL;
    cudaGetSymbolAddress((void**)&xf,  g_xf);
    cudaGetSymbolAddress((void**)&s0f, g_s0f);
    cudaGetSymbolAddress((void**)&s1f, g_s1f);
    cudaGetSymbolAddress((void**)&s2f, g_s2f);
    cudaGetSymbolAddress((void**)&s3f, g_s3f);
    cudaGetSymbolAddress((void**)&Wth, g_Wth); cudaGetSymbolAddress((void**)&Wtl, g_Wtl);
    cudaGetSymbolAddress((void**)&Pth, g_Pth); cudaGetSymbolAddress((void**)&Ptl, g_Ptl);
    cudaGetSymbolAddress((void**)&T1h, g_T1h); cudaGetSymbolAddress((void**)&T1l, g_T1l);
    cudaGetSymbolAddress((void**)&T3h, g_T3h); cudaGetSymbolAddress((void**)&T3l, g_T3l);
    cudaGetSymbolAddress((void**)&pP,  g_P);   cudaGetSymbolAddress((void**)&pT1p, g_T1p);
    cudaGetSymbolAddress((void**)&pT3p, g_T3p); cudaGetSymbolAddress((void**)&pOL, g_OL);

    cudaFuncSetAttribute(hgemm<false>, cudaFuncAttributeMaxDynamicSharedMemorySize, GEMM_SMEM);
    cudaFuncSetAttribute(hgemm<true>,  cudaFuncAttributeMaxDynamicSharedMemorySize, GEMM_SMEM);

    // Launch order: 4th launch (ncu capture) = G1.
    cvtA<<<1024, 256>>>(x,  xf,  (size_t)NN * DD / 4);                                   // 1
    cst<<<dim3(DD / 32, 16), dim3(32, 8)>>>(w, 1, DD, Wth, Wtl, alpha, -1);              // 2
    cvtA<<<2048, 256>>>(s3, s3f, (size_t)NH * NN / 4);                                   // 3
    // G1: P = x @ W        [8192,512], K=512                                  <- profiled
    hgemm<false><<<dim3(4, 32, 1), 256, GEMM_SMEM>>>(xf, Wth, Wtl, pP, NN, DD,           // 4
                                                     nullptr, nullptr);
    cst<<<dim3(NN / 32, 16), dim3(32, 8)>>>(pP, 1, NN, Pth, Ptl, alpha, -1);             // 5
    // G4: T3 = s3 @ P      [6144,512], K=8192, split-K=3
    hgemm<false><<<dim3(4, 24, 3), 256, GEMM_SMEM>>>(s3f, Pth, Ptl, pT3p, NH, NN,        // 6
                                                     nullptr, nullptr);
    cvtA<<<1024, 256>>>(s1, s1f, (size_t)KK * NN / 4);                                   // 7
    // G2: T1 = s1 @ P      [2048,512], K=8192, split-K=4
    hgemm<false><<<dim3(4, 8, 4), 256, GEMM_SMEM>>>(s1f, Pth, Ptl, pT1p, KK, NN,         // 8
                                                    nullptr, nullptr);
    cst<<<dim3(KK / 32, 16), dim3(32, 8)>>>(pT1p, 4, KK, T1h, T1l, alpha, 0);            // 9
    cvtA<<<1024, 256>>>(s0, s0f, (size_t)NN * KK / 4);                                   // 10
    // G3: OL = s0 @ T1     [8192,512], K=2048
    hgemm<false><<<dim3(4, 32, 1), 256, GEMM_SMEM>>>(s0f, T1h, T1l, pOL, NN, KK,         // 11
                                                     nullptr, nullptr);
    cst<<<dim3(NH / 32, 16), dim3(32, 8)>>>(pT3p, 3, NH, T3h, T3l, alpha, 1);            // 12
    cvtA<<<2048, 256>>>(s2, s2f, (size_t)NN * NH / 4);                                   // 13
    // G5: out = relu(max(OL, s2 @ T3) + bias)   [8192,512], K=6144
    hgemm<true><<<dim3(4, 32, 1), 256, GEMM_SMEM>>>(s2f, T3h, T3l, out, NN, NH,          // 14
                                                    pOL, bias);
}

// round 10
// speedup vs baseline: 5.2978x; 1.2134x over previous
#include <cuda_runtime.h>
#include <cuda_fp16.h>
#include <cstdint>
#include <cstddef>

#define DINL __device__ __forceinline__

// ------------------------- problem sizes -------------------------
#define NN 8192
#define KK 2048
#define DD 512
#define NH (NN - KK)   // 6144

// ------------------------- scratch (static device globals) -------------------------
__device__ __half g_xf [NN*DD];
__device__ __half g_s0f[NN*KK];
__device__ __half g_s1f[KK*NN];
__device__ __half g_s2f[(size_t)NN*NH];
__device__ __half g_s3f[(size_t)NH*NN];
__device__ __half g_Wth[DD*DD],  g_Wtl[DD*DD];
__device__ __half g_Pth[DD*NN],  g_Ptl[DD*NN];
__device__ __half g_T1h[DD*KK],  g_T1l[DD*KK];
__device__ __half g_T3h[DD*NH],  g_T3l[DD*NH];
__device__ float g_P  [NN*DD];
__device__ float g_T1p[4*KK*DD];
__device__ float g_T3p[3*NH*DD];
__device__ float g_OL [NN*DD];

// ------------------------- ptx helpers (base ISA only) ----
DINL uint32_t smem_u32(const void* p) {
    uint32_t a;
    asm("{ .reg .u64 t; cvta.to.shared.u64 t, %1; cvt.u32.u64 %0, t; }" : "=r"(a) : "l"(p));
    return a;
}
DINL void cp16(uint32_t saddr, const void* g) {
    asm volatile("cp.async.cg.shared.global [%0], [%1], 16;" :: "r"(saddr), "l"(g));
}
DINL void cp_commit() { asm volatile("cp.async.commit_group;" ::: "memory"); }
DINL void cp_wait1()  { asm volatile("cp.async.wait_group 1;" ::: "memory"); }
DINL void cp_wait0()  { asm volatile("cp.async.wait_group 0;" ::: "memory"); }

DINL void ldsm4(uint32_t (&r)[4], uint32_t addr) {
    asm volatile("ldmatrix.sync.aligned.m8n8.x4.shared.b16 {%0,%1,%2,%3}, [%4];"
                 : "=r"(r[0]), "=r"(r[1]), "=r"(r[2]), "=r"(r[3]) : "r"(addr));
}
DINL void mma_f16(float (&d)[4], const uint32_t (&a)[4], const uint32_t* b) {
    asm volatile(
        "mma.sync.aligned.m16n8k16.row.col.f32.f16.f16.f32 "
        "{%0,%1,%2,%3}, {%4,%5,%6,%7}, {%8,%9}, {%0,%1,%2,%3};"
        : "+f"(d[0]), "+f"(d[1]), "+f"(d[2]), "+f"(d[3])
        : "r"(a[0]), "r"(a[1]), "r"(a[2]), "r"(a[3]), "r"(b[0]), "r"(b[1]));
}

// ------------------------- GEMM -------------------------
// C[z][M,512] = A[M,K] @ Bt^T, A single fp16; Bt fp16 hi(/lo) — NPASS∈{1,2}.
// CTA tile 256x128, BK=64 (128B SW128 rows), 8 warps of 64x64, 2-stage cp.async.
static constexpr int OFF_A  = 0;       // 32 KB (256 rows x 128B)
static constexpr int OFF_BH = 32768;   // 16 KB
static constexpr int OFF_BL = 49152;   // 16 KB (NPASS==2 only)

template <int NPASS> struct StageCfg {
    static constexpr int STAGE = (NPASS == 2) ? 65536 : 49152;
    static constexpr int SMEM  = 2 * STAGE;
};

DINL void ld_sec(uint32_t sdst, const char* src, int row0, size_t pitch,
                 size_t kbyte, int nIter, int tid)
{
    for (int i = 0; i < nIter; i++) {
        int idx = tid * 16 + i * 4096;
        int row = idx >> 7, col = idx & 127;
        uint32_t sw = (uint32_t)idx ^ (((uint32_t)idx >> 3) & 0x70);
        cp16(sdst + sw, src + (size_t)(row0 + row) * pitch + kbyte + col);
    }
}

template <bool FINAL, int NPASS>
__global__ void __launch_bounds__(256, 1)
hgemm(const __half* __restrict__ A_,
      const __half* __restrict__ Bh_, const __half* __restrict__ Bl_,
      float* __restrict__ C, int M, int K,
      const float* __restrict__ other, const float* __restrict__ bias)
{
    constexpr int STAGE_BYTES = StageCfg<NPASS>::STAGE;
    extern __shared__ char smem[];
    const uint32_t sb0 = smem_u32(smem);
    const int tid = threadIdx.x, wid = tid >> 5, lane = tid & 31;
    const int brow = blockIdx.y * 256, bcol = blockIdx.x * 128;
    const int warpM = (wid & 3) * 64, warpN = (wid >> 2) * 64;

    const int kchunks = K >> 6;
    const int Z = gridDim.z, z = blockIdx.z;
    const int kc0 = (int)(((long long)kchunks * z) / Z);
    const int kc1 = (int)(((long long)kchunks * (z + 1)) / Z);
    const int total = kc1 - kc0;
    float* Cz = C + (size_t)z * M * 512;

    const char* A  = (const char*)A_;
    const char* Bh = (const char*)Bh_;
    const char* Bl = (const char*)Bl_;
    const size_t pitch = (size_t)K * 2;

    const uint32_t xorv = (uint32_t)(lane & 7) << 4;
    const uint32_t kaA = ((lane >> 4) & 1) * 16;
    const uint32_t kbB = ((lane >> 3) & 1) * 16;
    uint32_t aRowOff[4], bRowOff[4];
#pragma unroll
    for (int am = 0; am < 4; am++)
        aRowOff[am] = (uint32_t)(warpM + am * 16 + (lane & 15)) * 128;
#pragma unroll
    for (int bg = 0; bg < 4; bg++)
        bRowOff[bg] = (uint32_t)(warpN + bg * 16 + ((lane >> 4) & 1) * 8 + (lane & 7)) * 128;

    float acc[4][8][4];
#pragma unroll
    for (int i = 0; i < 4; i++)
#pragma unroll
        for (int j = 0; j < 8; j++)
#pragma unroll
            for (int t = 0; t < 4; t++) acc[i][j][t] = 0.0f;

    // pipeline prologue: fill both stages
#pragma unroll 1
    for (int p = 0; p < 2; p++) {
        uint32_t sb = sb0 + p * STAGE_BYTES;
        size_t kb = (size_t)(kc0 + p) * 128;
        ld_sec(sb + OFF_A,  A,  brow, pitch, kb, 8, tid);
        ld_sec(sb + OFF_BH, Bh, bcol, pitch, kb, 4, tid);
        if (NPASS == 2) ld_sec(sb + OFF_BL, Bl, bcol, pitch, kb, 4, tid);
        cp_commit();
    }

#pragma unroll 1
    for (int it = 0; it < total; ++it) {
        const int s = it & 1;
        if (it < total - 1) cp_wait1(); else cp_wait0();
        __syncthreads();

        const uint32_t sb = sb0 + s * STAGE_BYTES;
#pragma unroll 1
        for (int ks = 0; ks < 4; ks++) {
            const uint32_t kA = ((uint32_t)(ks * 32) + kaA) ^ xorv;
            const uint32_t kB = ((uint32_t)(ks * 32) + kbB) ^ xorv;
            uint32_t ah[4][4];
#pragma unroll
            for (int am = 0; am < 4; am++)
                ldsm4(ah[am], sb + OFF_A + aRowOff[am] + kA);
#pragma unroll
            for (int bg = 0; bg < 4; bg++) {
                uint32_t bh[4], bl[4];
                ldsm4(bh, sb + OFF_BH + bRowOff[bg] + kB);
                if (NPASS == 2) ldsm4(bl, sb + OFF_BL + bRowOff[bg] + kB);
#pragma unroll
                for (int am = 0; am < 4; am++)
#pragma unroll
                    for (int h = 0; h < 2; h++)
                        mma_f16(acc[am][bg * 2 + h], ah[am], bh + h * 2);
                if (NPASS == 2) {
#pragma unroll
                    for (int am = 0; am < 4; am++)
#pragma unroll
                        for (int h = 0; h < 2; h++)
                            mma_f16(acc[am][bg * 2 + h], ah[am], bl + h * 2);
                }
            }
        }
        __syncthreads();
        const int nx = it + 2;
        if (nx < total) {
            size_t kb = (size_t)(kc0 + nx) * 128;
            ld_sec(sb + OFF_A,  A,  brow, pitch, kb, 8, tid);
            ld_sec(sb + OFF_BH, Bh, bcol, pitch, kb, 4, tid);
            if (NPASS == 2) ld_sec(sb + OFF_BL, Bl, bcol, pitch, kb, 4, tid);
            cp_commit();
        }
    }

    // epilogue
#pragma unroll
    for (int am = 0; am < 4; am++) {
#pragma unroll
        for (int bn = 0; bn < 8; bn++) {
            const int r0 = brow + warpM + am * 16 + (lane >> 2);
            const int cg = bcol + warpN + bn * 8 + (lane & 3) * 2;
#pragma unroll
            for (int h = 0; h < 2; h++) {
                const int row = r0 + h * 8;
                float2 v = make_float2(acc[am][bn][h * 2], acc[am][bn][h * 2 + 1]);
                size_t o = (size_t)row * 512 + cg;
                if (FINAL) {
                    float2 ov = *(const float2*)(other + o);
                    float2 bb = *(const float2*)(bias + cg);
                    v.x = fmaxf(fmaxf(v.x, ov.x) + bb.x, 0.0f);
                    v.y = fmaxf(fmaxf(v.y, ov.y) + bb.y, 0.0f);
                }
                *(float2*)(Cz + o) = v;
            }
        }
    }
}

// ------------------------- convert fp32 -> fp16 (A operands) -------------------------
__global__ void cvtA(const float* __restrict__ src, __half* __restrict__ dst, size_t n4)
{
    size_t stride = (size_t)gridDim.x * blockDim.x;
    for (size_t i = (size_t)blockIdx.x * blockDim.x + threadIdx.x; i < n4; i += stride) {
        float4 v = ((const float4*)src)[i];
        __half2 p0 = __floats2half2_rn(v.x, v.y);
        __half2 p1 = __floats2half2_rn(v.z, v.w);
        uint2 o;
        o.x = *(const uint32_t*)&p0;
        o.y = *(const uint32_t*)&p1;
        ((uint2*)dst)[i] = o;
    }
}

// ------------- combine(split-K) + scale + transpose + fp16 hi/lo split -------------
__global__ void cst(const float* __restrict__ parts, int Z, int Min,
                    __half* __restrict__ th, __half* __restrict__ tl,
                    const float* __restrict__ alpha, int aidx)
{
    __shared__ float tile[32][33];
    const int m0 = blockIdx.x * 32, n0 = blockIdx.y * 32;
    const int tx = threadIdx.x, ty = threadIdx.y;   // 32 x 8
    float s = 1.0f;
    if (aidx >= 0) {
        float e0 = __expf(alpha[0]), e1 = __expf(alpha[1]);
        s = (aidx == 0 ? e0 : e1) / (e0 + e1);
    }
#pragma unroll
    for (int j = 0; j < 32; j += 8) {
        int m = m0 + ty + j;
        float acc = 0.0f;
        for (int zz = 0; zz < Z; zz++)
            acc += parts[((size_t)zz * Min + m) * 512 + n0 + tx];
        tile[ty + j][tx] = acc * s;
    }
    __syncthreads();
#pragma unroll
    for (int j = 0; j < 32; j += 8) {
        float v = tile[tx][ty + j];
        __half h = __float2half_rn(v);
        __half l = __float2half_rn(v - __half2float(h));
        size_t o = (size_t)(n0 + ty + j) * Min + m0 + tx;
        th[o] = h;
        tl[o] = l;
    }
}

// ------------------------- host -------------------------
extern "C" void kernel_launch(void* const* d_in, const int* in_sizes, int n_in,
                              void* d_out, int out_size)
{
    const float* x     = (const float*)d_in[0];
    const float* w     = (const float*)d_in[1];
    const float* alpha = (const float*)d_in[2];
    const float* bias  = (const float*)d_in[3];
    const float* s0    = (const float*)d_in[4];
    const float* s1    = (const float*)d_in[5];
    const float* s2    = (const float*)d_in[6];
    const float* s3    = (const float*)d_in[7];
    float* out = (float*)d_out;

    __half *xf, *s0f, *s1f, *s2f, *s3f;
    __half *Wth, *Wtl, *Pth, *Ptl, *T1h, *T1l, *T3h, *T3l;
    float *pP, *pT1p, *pT3p, *pOL;
    cudaGetSymbolAddress((void**)&xf,  g_xf);
    cudaGetSymbolAddress((void**)&s0f, g_s0f);
    cudaGetSymbolAddress((void**)&s1f, g_s1f);
    cudaGetSymbolAddress((void**)&s2f, g_s2f);
    cudaGetSymbolAddress((void**)&s3f, g_s3f);
    cudaGetSymbolAddress((void**)&Wth, g_Wth); cudaGetSymbolAddress((void**)&Wtl, g_Wtl);
    cudaGetSymbolAddress((void**)&Pth, g_Pth); cudaGetSymbolAddress((void**)&Ptl, g_Ptl);
    cudaGetSymbolAddress((void**)&T1h, g_T1h); cudaGetSymbolAddress((void**)&T1l, g_T1l);
    cudaGetSymbolAddress((void**)&T3h, g_T3h); cudaGetSymbolAddress((void**)&T3l, g_T3l);
    cudaGetSymbolAddress((void**)&pP,  g_P);   cudaGetSymbolAddress((void**)&pT1p, g_T1p);
    cudaGetSymbolAddress((void**)&pT3p, g_T3p); cudaGetSymbolAddress((void**)&pOL, g_OL);

    cudaFuncSetAttribute((const void*)hgemm<false, 2>,
                         cudaFuncAttributeMaxDynamicSharedMemorySize, StageCfg<2>::SMEM);
    cudaFuncSetAttribute((const void*)hgemm<false, 1>,
                         cudaFuncAttributeMaxDynamicSharedMemorySize, StageCfg<1>::SMEM);
    cudaFuncSetAttribute((const void*)hgemm<true, 1>,
                         cudaFuncAttributeMaxDynamicSharedMemorySize, StageCfg<1>::SMEM);

    // Launch order: 4th launch (ncu capture) = G1.
    cvtA<<<1024, 256>>>(x,  xf,  (size_t)NN * DD / 4);                                   // 1
    cst<<<dim3(DD / 32, 16), dim3(32, 8)>>>(w, 1, DD, Wth, Wtl, alpha, -1);              // 2
    cvtA<<<2048, 256>>>(s3, s3f, (size_t)NH * NN / 4);                                   // 3
    // G1: P = x @ W        [8192,512], K=512, 2-pass B                        <- profiled
    hgemm<false, 2><<<dim3(4, 32, 1), 256, StageCfg<2>::SMEM>>>(xf, Wth, Wtl, pP,        // 4
                                                                NN, DD, nullptr, nullptr);
    cst<<<dim3(NN / 32, 16), dim3(32, 8)>>>(pP, 1, NN, Pth, Ptl, alpha, -1);             // 5
    // G4: T3 = s3 @ P      [6144,512], K=8192, split-K=3, 2-pass B
    hgemm<false, 2><<<dim3(4, 24, 3), 256, StageCfg<2>::SMEM>>>(s3f, Pth, Ptl, pT3p,     // 6
                                                                NH, NN, nullptr, nullptr);
    cvtA<<<1024, 256>>>(s1, s1f, (size_t)KK * NN / 4);                                   // 7
    // G2: T1 = s1 @ P      [2048,512], K=8192, split-K=4, 2-pass B
    hgemm<false, 2><<<dim3(4, 8, 4), 256, StageCfg<2>::SMEM>>>(s1f, Pth, Ptl, pT1p,      // 8
                                                               KK, NN, nullptr, nullptr);
    cst<<<dim3(KK / 32, 16), dim3(32, 8)>>>(pT1p, 4, KK, T1h, T1l, alpha, 0);            // 9
    cvtA<<<1024, 256>>>(s0, s0f, (size_t)NN * KK / 4);                                   // 10
    // G3: OL = s0 @ T1     [8192,512], K=2048, 1-pass B (final layer)
    hgemm<false, 1><<<dim3(4, 32, 1), 256, StageCfg<1>::SMEM>>>(s0f, T1h, T1l, pOL,      // 11
                                                                NN, KK, nullptr, nullptr);
    cst<<<dim3(NH / 32, 16), dim3(32, 8)>>>(pT3p, 3, NH, T3h, T3l, alpha, 1);            // 12
    cvtA<<<2048, 256>>>(s2, s2f, (size_t)NN * NH / 4);                                   // 13
    // G5: out = relu(max(OL, s2 @ T3) + bias)   [8192,512], K=6144, 1-pass B (final layer)
    hgemm<true, 1><<<dim3(4, 32, 1), 256, StageCfg<1>::SMEM>>>(s2f, T3h, T3l, out,       // 14
                                                               NN, NH, pOL, bias);
}

// round 11
// speedup vs baseline: 6.5834x; 1.2427x over previous
#include <cuda_runtime.h>
#include <cuda_fp16.h>
#include <cstdint>
#include <cstddef>

#define DINL __device__ __forceinline__

// ------------------------- problem sizes -------------------------
#define NN 8192
#define KK 2048
#define DD 512
#define NH (NN - KK)   // 6144

// ------------------------- scratch (static device globals) -------------------------
__device__ __half g_xf [NN*DD];
__device__ __half g_s0f[NN*KK];
__device__ __half g_s1f[KK*NN];
__device__ __half g_s2f[(size_t)NN*NH];
__device__ __half g_s3f[(size_t)NH*NN];
__device__ __half g_Wth[DD*DD],  g_Wtl[DD*DD];
__device__ __half g_Pth[DD*NN];
__device__ __half g_T1h[DD*KK];
__device__ __half g_T3h[DD*NH];
__device__ float g_P  [NN*DD];
__device__ float g_T1p[4*KK*DD];
__device__ float g_T3p[3*NH*DD];
__device__ float g_OL [NN*DD];

// ------------------------- ptx helpers (base ISA only) ----
DINL uint32_t smem_u32(const void* p) {
    uint32_t a;
    asm("{ .reg .u64 t; cvta.to.shared.u64 t, %1; cvt.u32.u64 %0, t; }" : "=r"(a) : "l"(p));
    return a;
}
DINL void cp16(uint32_t saddr, const void* g) {
    asm volatile("cp.async.cg.shared.global [%0], [%1], 16;" :: "r"(saddr), "l"(g));
}
DINL void cp_commit() { asm volatile("cp.async.commit_group;" ::: "memory"); }
DINL void cp_wait1()  { asm volatile("cp.async.wait_group 1;" ::: "memory"); }
DINL void cp_wait0()  { asm volatile("cp.async.wait_group 0;" ::: "memory"); }

DINL void ldsm4(uint32_t (&r)[4], uint32_t addr) {
    asm volatile("ldmatrix.sync.aligned.m8n8.x4.shared.b16 {%0,%1,%2,%3}, [%4];"
                 : "=r"(r[0]), "=r"(r[1]), "=r"(r[2]), "=r"(r[3]) : "r"(addr));
}
DINL void mma_f16(float (&d)[4], const uint32_t (&a)[4], const uint32_t* b) {
    asm volatile(
        "mma.sync.aligned.m16n8k16.row.col.f32.f16.f16.f32 "
        "{%0,%1,%2,%3}, {%4,%5,%6,%7}, {%8,%9}, {%0,%1,%2,%3};"
        : "+f"(d[0]), "+f"(d[1]), "+f"(d[2]), "+f"(d[3])
        : "r"(a[0]), "r"(a[1]), "r"(a[2]), "r"(a[3]), "r"(b[0]), "r"(b[1]));
}

// ------------------------- GEMM -------------------------
// C[z][M,512] = A[M,K] @ Bt^T, A single fp16; Bt fp16 hi(/lo) — NPASS∈{1,2}.
// CTA tile 256x128, BK=64 (128B SW128 rows), 8 warps of 64x64, 2-stage cp.async.
static constexpr int OFF_A  = 0;       // 32 KB (256 rows x 128B)
static constexpr int OFF_BH = 32768;   // 16 KB
static constexpr int OFF_BL = 49152;   // 16 KB (NPASS==2 only)

template <int NPASS> struct StageCfg {
    static constexpr int STAGE = (NPASS == 2) ? 65536 : 49152;
    static constexpr int SMEM  = 2 * STAGE;
};

DINL void ld_sec(uint32_t sdst, const char* src, int row0, size_t pitch,
                 size_t kbyte, int nIter, int tid)
{
    for (int i = 0; i < nIter; i++) {
        int idx = tid * 16 + i * 4096;
        int row = idx >> 7, col = idx & 127;
        uint32_t sw = (uint32_t)idx ^ (((uint32_t)idx >> 3) & 0x70);
        cp16(sdst + sw, src + (size_t)(row0 + row) * pitch + kbyte + col);
    }
}

template <bool FINAL, int NPASS>
__global__ void __launch_bounds__(256, 1)
hgemm(const __half* __restrict__ A_,
      const __half* __restrict__ Bh_, const __half* __restrict__ Bl_,
      float* __restrict__ C, int M, int K,
      const float* __restrict__ other, const float* __restrict__ bias)
{
    constexpr int STAGE_BYTES = StageCfg<NPASS>::STAGE;
    extern __shared__ char smem[];
    const uint32_t sb0 = smem_u32(smem);
    const int tid = threadIdx.x, wid = tid >> 5, lane = tid & 31;
    const int brow = blockIdx.y * 256, bcol = blockIdx.x * 128;
    const int warpM = (wid & 3) * 64, warpN = (wid >> 2) * 64;

    const int kchunks = K >> 6;
    const int Z = gridDim.z, z = blockIdx.z;
    const int kc0 = (int)(((long long)kchunks * z) / Z);
    const int kc1 = (int)(((long long)kchunks * (z + 1)) / Z);
    const int total = kc1 - kc0;
    float* Cz = C + (size_t)z * M * 512;

    const char* A  = (const char*)A_;
    const char* Bh = (const char*)Bh_;
    const char* Bl = (const char*)Bl_;
    const size_t pitch = (size_t)K * 2;

    const uint32_t xorv = (uint32_t)(lane & 7) << 4;
    const uint32_t kaA = ((lane >> 4) & 1) * 16;
    const uint32_t kbB = ((lane >> 3) & 1) * 16;
    uint32_t aRowOff[4], bRowOff[4];
#pragma unroll
    for (int am = 0; am < 4; am++)
        aRowOff[am] = (uint32_t)(warpM + am * 16 + (lane & 15)) * 128;
#pragma unroll
    for (int bg = 0; bg < 4; bg++)
        bRowOff[bg] = (uint32_t)(warpN + bg * 16 + ((lane >> 4) & 1) * 8 + (lane & 7)) * 128;

    float acc[4][8][4];
#pragma unroll
    for (int i = 0; i < 4; i++)
#pragma unroll
        for (int j = 0; j < 8; j++)
#pragma unroll
            for (int t = 0; t < 4; t++) acc[i][j][t] = 0.0f;

    // pipeline prologue: fill both stages
#pragma unroll 1
    for (int p = 0; p < 2; p++) {
        uint32_t sb = sb0 + p * STAGE_BYTES;
        size_t kb = (size_t)(kc0 + p) * 128;
        ld_sec(sb + OFF_A,  A,  brow, pitch, kb, 8, tid);
        ld_sec(sb + OFF_BH, Bh, bcol, pitch, kb, 4, tid);
        if (NPASS == 2) ld_sec(sb + OFF_BL, Bl, bcol, pitch, kb, 4, tid);
        cp_commit();
    }

#pragma unroll 1
    for (int it = 0; it < total; ++it) {
        const int s = it & 1;
        if (it < total - 1) cp_wait1(); else cp_wait0();
        __syncthreads();

        const uint32_t sb = sb0 + s * STAGE_BYTES;
#pragma unroll 1
        for (int ks = 0; ks < 4; ks++) {
            const uint32_t kA = ((uint32_t)(ks * 32) + kaA) ^ xorv;
            const uint32_t kB = ((uint32_t)(ks * 32) + kbB) ^ xorv;
            uint32_t ah[4][4];
#pragma unroll
            for (int am = 0; am < 4; am++)
                ldsm4(ah[am], sb + OFF_A + aRowOff[am] + kA);
#pragma unroll
            for (int bg = 0; bg < 4; bg++) {
                uint32_t bh[4], bl[4];
                ldsm4(bh, sb + OFF_BH + bRowOff[bg] + kB);
                if (NPASS == 2) ldsm4(bl, sb + OFF_BL + bRowOff[bg] + kB);
#pragma unroll
                for (int am = 0; am < 4; am++)
#pragma unroll
                    for (int h = 0; h < 2; h++)
                        mma_f16(acc[am][bg * 2 + h], ah[am], bh + h * 2);
                if (NPASS == 2) {
#pragma unroll
                    for (int am = 0; am < 4; am++)
#pragma unroll
                        for (int h = 0; h < 2; h++)
                            mma_f16(acc[am][bg * 2 + h], ah[am], bl + h * 2);
                }
            }
        }
        __syncthreads();
        const int nx = it + 2;
        if (nx < total) {
            size_t kb = (size_t)(kc0 + nx) * 128;
            ld_sec(sb + OFF_A,  A,  brow, pitch, kb, 8, tid);
            ld_sec(sb + OFF_BH, Bh, bcol, pitch, kb, 4, tid);
            if (NPASS == 2) ld_sec(sb + OFF_BL, Bl, bcol, pitch, kb, 4, tid);
            cp_commit();
        }
    }

    // epilogue
#pragma unroll
    for (int am = 0; am < 4; am++) {
#pragma unroll
        for (int bn = 0; bn < 8; bn++) {
            const int r0 = brow + warpM + am * 16 + (lane >> 2);
            const int cg = bcol + warpN + bn * 8 + (lane & 3) * 2;
#pragma unroll
            for (int h = 0; h < 2; h++) {
                const int row = r0 + h * 8;
                float2 v = make_float2(acc[am][bn][h * 2], acc[am][bn][h * 2 + 1]);
                size_t o = (size_t)row * 512 + cg;
                if (FINAL) {
                    float2 ov = *(const float2*)(other + o);
                    float2 bb = *(const float2*)(bias + cg);
                    v.x = fmaxf(fmaxf(v.x, ov.x) + bb.x, 0.0f);
                    v.y = fmaxf(fmaxf(v.y, ov.y) + bb.y, 0.0f);
                }
                *(float2*)(Cz + o) = v;
            }
        }
    }
}

// ------------------------- convert fp32 -> fp16 (A operands) -------------------------
__global__ void cvtA(const float* __restrict__ src, __half* __restrict__ dst, size_t n4)
{
    size_t stride = (size_t)gridDim.x * blockDim.x;
    for (size_t i = (size_t)blockIdx.x * blockDim.x + threadIdx.x; i < n4; i += stride) {
        float4 v = ((const float4*)src)[i];
        __half2 p0 = __floats2half2_rn(v.x, v.y);
        __half2 p1 = __floats2half2_rn(v.z, v.w);
        uint2 o;
        o.x = *(const uint32_t*)&p0;
        o.y = *(const uint32_t*)&p1;
        ((uint2*)dst)[i] = o;
    }
}

// ------------- combine(split-K) + scale + transpose + fp16 (hi, optional lo) -------------
__global__ void cst(const float* __restrict__ parts, int Z, int Min,
                    __half* __restrict__ th, __half* __restrict__ tl,
                    const float* __restrict__ alpha, int aidx)
{
    __shared__ float tile[32][33];
    const int m0 = blockIdx.x * 32, n0 = blockIdx.y * 32;
    const int tx = threadIdx.x, ty = threadIdx.y;   // 32 x 8
    float s = 1.0f;
    if (aidx >= 0) {
        float e0 = __expf(alpha[0]), e1 = __expf(alpha[1]);
        s = (aidx == 0 ? e0 : e1) / (e0 + e1);
    }
#pragma unroll
    for (int j = 0; j < 32; j += 8) {
        int m = m0 + ty + j;
        float acc = 0.0f;
        for (int zz = 0; zz < Z; zz++)
            acc += parts[((size_t)zz * Min + m) * 512 + n0 + tx];
        tile[ty + j][tx] = acc * s;
    }
    __syncthreads();
#pragma unroll
    for (int j = 0; j < 32; j += 8) {
        float v = tile[tx][ty + j];
        __half h = __float2half_rn(v);
        size_t o = (size_t)(n0 + ty + j) * Min + m0 + tx;
        th[o] = h;
        if (tl) tl[o] = __float2half_rn(v - __half2float(h));
    }
}

// ------------------------- host -------------------------
extern "C" void kernel_launch(void* const* d_in, const int* in_sizes, int n_in,
                              void* d_out, int out_size)
{
    const float* x     = (const float*)d_in[0];
    const float* w     = (const float*)d_in[1];
    const float* alpha = (const float*)d_in[2];
    const float* bias  = (const float*)d_in[3];
    const float* s0    = (const float*)d_in[4];
    const float* s1    = (const float*)d_in[5];
    const float* s2    = (const float*)d_in[6];
    const float* s3    = (const float*)d_in[7];
    float* out = (float*)d_out;

    __half *xf, *s0f, *s1f, *s2f, *s3f;
    __half *Wth, *Wtl, *Pth, *T1h, *T3h;
    float *pP, *pT1p, *pT3p, *pOL;
    cudaGetSymbolAddress((void**)&xf,  g_xf);
    cudaGetSymbolAddress((void**)&s0f, g_s0f);
    cudaGetSymbolAddress((void**)&s1f, g_s1f);
    cudaGetSymbolAddress((void**)&s2f, g_s2f);
    cudaGetSymbolAddress((void**)&s3f, g_s3f);
    cudaGetSymbolAddress((void**)&Wth, g_Wth); cudaGetSymbolAddress((void**)&Wtl, g_Wtl);
    cudaGetSymbolAddress((void**)&Pth, g_Pth);
    cudaGetSymbolAddress((void**)&T1h, g_T1h);
    cudaGetSymbolAddress((void**)&T3h, g_T3h);
    cudaGetSymbolAddress((void**)&pP,  g_P);   cudaGetSymbolAddress((void**)&pT1p, g_T1p);
    cudaGetSymbolAddress((void**)&pT3p, g_T3p); cudaGetSymbolAddress((void**)&pOL, g_OL);

    cudaFuncSetAttribute((const void*)hgemm<false, 2>,
                         cudaFuncAttributeMaxDynamicSharedMemorySize, StageCfg<2>::SMEM);
    cudaFuncSetAttribute((const void*)hgemm<false, 1>,
                         cudaFuncAttributeMaxDynamicSharedMemorySize, StageCfg<1>::SMEM);
    cudaFuncSetAttribute((const void*)hgemm<true, 1>,
                         cudaFuncAttributeMaxDynamicSharedMemorySize, StageCfg<1>::SMEM);

    // Launch order: 4th launch (ncu capture) = G1.
    cvtA<<<1024, 256>>>(x,  xf,  (size_t)NN * DD / 4);                                   // 1
    cst<<<dim3(DD / 32, 16), dim3(32, 8)>>>(w, 1, DD, Wth, Wtl, alpha, -1);              // 2
    cvtA<<<2048, 256>>>(s3, s3f, (size_t)NH * NN / 4);                                   // 3
    // G1: P = x @ W        [8192,512], K=512, 2-pass B (W errors propagate everywhere)
    hgemm<false, 2><<<dim3(4, 32, 1), 256, StageCfg<2>::SMEM>>>(xf, Wth, Wtl, pP,        // 4
                                                                NN, DD, nullptr, nullptr);
    cst<<<dim3(NN / 32, 16), dim3(32, 8)>>>(pP, 1, NN, Pth, nullptr, alpha, -1);         // 5
    // G4: T3 = s3 @ P      [6144,512], K=8192, split-K=3, 1-pass B
    hgemm<false, 1><<<dim3(4, 24, 3), 256, StageCfg<1>::SMEM>>>(s3f, Pth, nullptr,       // 6
                                                                pT3p, NH, NN, nullptr, nullptr);
    cvtA<<<1024, 256>>>(s1, s1f, (size_t)KK * NN / 4);                                   // 7
    // G2: T1 = s1 @ P      [2048,512], K=8192, split-K=4, 1-pass B
    hgemm<false, 1><<<dim3(4, 8, 4), 256, StageCfg<1>::SMEM>>>(s1f, Pth, nullptr,        // 8
                                                               pT1p, KK, NN, nullptr, nullptr);
    cst<<<dim3(KK / 32, 16), dim3(32, 8)>>>(pT1p, 4, KK, T1h, nullptr, alpha, 0);        // 9
    cvtA<<<1024, 256>>>(s0, s0f, (size_t)NN * KK / 4);                                   // 10
    // G3: OL = s0 @ T1     [8192,512], K=2048, 1-pass B (final layer)
    hgemm<false, 1><<<dim3(4, 32, 1), 256, StageCfg<1>::SMEM>>>(s0f, T1h, nullptr, pOL,  // 11
                                                                NN, KK, nullptr, nullptr);
    cst<<<dim3(NH / 32, 16), dim3(32, 8)>>>(pT3p, 3, NH, T3h, nullptr, alpha, 1);        // 12
    cvtA<<<2048, 256>>>(s2, s2f, (size_t)NN * NH / 4);                                   // 13
    // G5: out = relu(max(OL, s2 @ T3) + bias)   [8192,512], K=6144, 1-pass B (final layer)
    hgemm<true, 1><<<dim3(4, 32, 1), 256, StageCfg<1>::SMEM>>>(s2f, T3h, nullptr, out,   // 14
                                                               NN, NH, pOL, bias);
}

// round 12
// speedup vs baseline: 6.8353x; 1.0383x over previous
#include <cuda_runtime.h>
#include <cuda_fp16.h>
#include <cstdint>
#include <cstddef>

#define DINL __device__ __forceinline__

// ------------------------- problem sizes -------------------------
#define NN 8192
#define KK 2048
#define DD 512
#define NH (NN - KK)   // 6144

// ------------------------- scratch (static device globals) -------------------------
__device__ __half g_xf [NN*DD];
__device__ __half g_s0f[NN*KK];
__device__ __half g_s1f[KK*NN];
__device__ __half g_s2f[(size_t)NN*NH];
__device__ __half g_s3f[(size_t)NH*NN];
__device__ __half g_Wth[DD*DD],  g_Wtl[DD*DD];
__device__ __half g_Pth[DD*NN];
__device__ __half g_T1h[DD*KK];
__device__ __half g_T3h[DD*NH];
__device__ float g_P  [NN*DD];
__device__ float g_T1p[4*KK*DD];
__device__ float g_T3p[3*NH*DD];
__device__ float g_OL [NN*DD];

// ------------------------- ptx helpers (base ISA only) ----
DINL uint32_t smem_u32(const void* p) {
    uint32_t a;
    asm("{ .reg .u64 t; cvta.to.shared.u64 t, %1; cvt.u32.u64 %0, t; }" : "=r"(a) : "l"(p));
    return a;
}
DINL void cp16(uint32_t saddr, const void* g) {
    asm volatile("cp.async.cg.shared.global [%0], [%1], 16;" :: "r"(saddr), "l"(g));
}
DINL void cp_commit() { asm volatile("cp.async.commit_group;" ::: "memory"); }
DINL void cp_wait1()  { asm volatile("cp.async.wait_group 1;" ::: "memory"); }
DINL void cp_wait0()  { asm volatile("cp.async.wait_group 0;" ::: "memory"); }

DINL void ldsm4(uint32_t (&r)[4], uint32_t addr) {
    asm volatile("ldmatrix.sync.aligned.m8n8.x4.shared.b16 {%0,%1,%2,%3}, [%4];"
                 : "=r"(r[0]), "=r"(r[1]), "=r"(r[2]), "=r"(r[3]) : "r"(addr));
}
DINL void mma_f16(float (&d)[4], const uint32_t (&a)[4], const uint32_t* b) {
    asm volatile(
        "mma.sync.aligned.m16n8k16.row.col.f32.f16.f16.f32 "
        "{%0,%1,%2,%3}, {%4,%5,%6,%7}, {%8,%9}, {%0,%1,%2,%3};"
        : "+f"(d[0]), "+f"(d[1]), "+f"(d[2]), "+f"(d[3])
        : "r"(a[0]), "r"(a[1]), "r"(a[2]), "r"(a[3]), "r"(b[0]), "r"(b[1]));
}

// ------------------------- GEMM -------------------------
// C[z][M,512] = A[M,K] @ Bt^T, A single fp16; Bt fp16 hi(/lo) — NPASS∈{1,2}.
// CTA tile 256x128, BK=64 (128B SW128 rows), 8 warps of 64x64, 2-stage cp.async.
static constexpr int OFF_A  = 0;       // 32 KB (256 rows x 128B)
static constexpr int OFF_BH = 32768;   // 16 KB
static constexpr int OFF_BL = 49152;   // 16 KB (NPASS==2 only)

template <int NPASS> struct StageCfg {
    static constexpr int STAGE = (NPASS == 2) ? 65536 : 49152;
    static constexpr int SMEM  = 2 * STAGE;
};

DINL void ld_sec(uint32_t sdst, const char* src, int row0, size_t pitch,
                 size_t kbyte, int nIter, int tid)
{
    for (int i = 0; i < nIter; i++) {
        int idx = tid * 16 + i * 4096;
        int row = idx >> 7, col = idx & 127;
        uint32_t sw = (uint32_t)idx ^ (((uint32_t)idx >> 3) & 0x70);
        cp16(sdst + sw, src + (size_t)(row0 + row) * pitch + kbyte + col);
    }
}

template <bool FINAL, int NPASS>
__global__ void __launch_bounds__(256, 1)
hgemm(const __half* __restrict__ A_,
      const __half* __restrict__ Bh_, const __half* __restrict__ Bl_,
      float* __restrict__ C, int M, int K,
      const float* __restrict__ other, const float* __restrict__ bias)
{
    constexpr int STAGE_BYTES = StageCfg<NPASS>::STAGE;
    extern __shared__ char smem[];
    const uint32_t sb0 = smem_u32(smem);
    const int tid = threadIdx.x, wid = tid >> 5, lane = tid & 31;
    const int brow = blockIdx.y * 256, bcol = blockIdx.x * 128;
    const int warpM = (wid & 3) * 64, warpN = (wid >> 2) * 64;

    const int kchunks = K >> 6;
    const int Z = gridDim.z, z = blockIdx.z;
    const int kc0 = (int)(((long long)kchunks * z) / Z);
    const int kc1 = (int)(((long long)kchunks * (z + 1)) / Z);
    const int total = kc1 - kc0;
    float* Cz = C + (size_t)z * M * 512;

    const char* A  = (const char*)A_;
    const char* Bh = (const char*)Bh_;
    const char* Bl = (const char*)Bl_;
    const size_t pitch = (size_t)K * 2;

    const uint32_t xorv = (uint32_t)(lane & 7) << 4;
    const uint32_t kaA = ((lane >> 4) & 1) * 16;
    const uint32_t kbB = ((lane >> 3) & 1) * 16;
    uint32_t aRowOff[4], bRowOff[4];
#pragma unroll
    for (int am = 0; am < 4; am++)
        aRowOff[am] = (uint32_t)(warpM + am * 16 + (lane & 15)) * 128;
#pragma unroll
    for (int bg = 0; bg < 4; bg++)
        bRowOff[bg] = (uint32_t)(warpN + bg * 16 + ((lane >> 4) & 1) * 8 + (lane & 7)) * 128;

    float acc[4][8][4];
#pragma unroll
    for (int i = 0; i < 4; i++)
#pragma unroll
        for (int j = 0; j < 8; j++)
#pragma unroll
            for (int t = 0; t < 4; t++) acc[i][j][t] = 0.0f;

    // pipeline prologue: fill both stages
#pragma unroll 1
    for (int p = 0; p < 2; p++) {
        uint32_t sb = sb0 + p * STAGE_BYTES;
        size_t kb = (size_t)(kc0 + p) * 128;
        ld_sec(sb + OFF_A,  A,  brow, pitch, kb, 8, tid);
        ld_sec(sb + OFF_BH, Bh, bcol, pitch, kb, 4, tid);
        if (NPASS == 2) ld_sec(sb + OFF_BL, Bl, bcol, pitch, kb, 4, tid);
        cp_commit();
    }

#pragma unroll 1
    for (int it = 0; it < total; ++it) {
        const int s = it & 1;
        if (it < total - 1) cp_wait1(); else cp_wait0();
        __syncthreads();

        const uint32_t sb = sb0 + s * STAGE_BYTES;
#pragma unroll 1
        for (int ks = 0; ks < 4; ks++) {
            const uint32_t kA = ((uint32_t)(ks * 32) + kaA) ^ xorv;
            const uint32_t kB = ((uint32_t)(ks * 32) + kbB) ^ xorv;
            uint32_t ah[4][4];
#pragma unroll
            for (int am = 0; am < 4; am++)
                ldsm4(ah[am], sb + OFF_A + aRowOff[am] + kA);
#pragma unroll
            for (int bg = 0; bg < 4; bg++) {
                uint32_t bh[4], bl[4];
                ldsm4(bh, sb + OFF_BH + bRowOff[bg] + kB);
                if (NPASS == 2) ldsm4(bl, sb + OFF_BL + bRowOff[bg] + kB);
#pragma unroll
                for (int am = 0; am < 4; am++)
#pragma unroll
                    for (int h = 0; h < 2; h++)
                        mma_f16(acc[am][bg * 2 + h], ah[am], bh + h * 2);
                if (NPASS == 2) {
#pragma unroll
                    for (int am = 0; am < 4; am++)
#pragma unroll
                        for (int h = 0; h < 2; h++)
                            mma_f16(acc[am][bg * 2 + h], ah[am], bl + h * 2);
                }
            }
        }
        __syncthreads();
        const int nx = it + 2;
        if (nx < total) {
            size_t kb = (size_t)(kc0 + nx) * 128;
            ld_sec(sb + OFF_A,  A,  brow, pitch, kb, 8, tid);
            ld_sec(sb + OFF_BH, Bh, bcol, pitch, kb, 4, tid);
            if (NPASS == 2) ld_sec(sb + OFF_BL, Bl, bcol, pitch, kb, 4, tid);
            cp_commit();
        }
    }

    // epilogue
#pragma unroll
    for (int am = 0; am < 4; am++) {
#pragma unroll
        for (int bn = 0; bn < 8; bn++) {
            const int r0 = brow + warpM + am * 16 + (lane >> 2);
            const int cg = bcol + warpN + bn * 8 + (lane & 3) * 2;
#pragma unroll
            for (int h = 0; h < 2; h++) {
                const int row = r0 + h * 8;
                float2 v = make_float2(acc[am][bn][h * 2], acc[am][bn][h * 2 + 1]);
                size_t o = (size_t)row * 512 + cg;
                if (FINAL) {
                    float2 ov = *(const float2*)(other + o);
                    float2 bb = *(const float2*)(bias + cg);
                    v.x = fmaxf(fmaxf(v.x, ov.x) + bb.x, 0.0f);
                    v.y = fmaxf(fmaxf(v.y, ov.y) + bb.y, 0.0f);
                }
                *(float2*)(Cz + o) = v;
            }
        }
    }
}

// ------------------------- convert fp32 -> fp16 (A operands) -------------------------
__global__ void cvtA(const float* __restrict__ src, __half* __restrict__ dst, size_t n4)
{
    size_t stride = (size_t)gridDim.x * blockDim.x;
    for (size_t i = (size_t)blockIdx.x * blockDim.x + threadIdx.x; i < n4; i += stride) {
        float4 v = ((const float4*)src)[i];
        __half2 p0 = __floats2half2_rn(v.x, v.y);
        __half2 p1 = __floats2half2_rn(v.z, v.w);
        uint2 o;
        o.x = *(const uint32_t*)&p0;
        o.y = *(const uint32_t*)&p1;
        ((uint2*)dst)[i] = o;
    }
}

// ------------- combine(split-K) + scale + transpose + fp16 (hi, optional lo) -------------
__global__ void cst(const float* __restrict__ parts, int Z, int Min,
                    __half* __restrict__ th, __half* __restrict__ tl,
                    const float* __restrict__ alpha, int aidx)
{
    __shared__ float tile[32][33];
    const int m0 = blockIdx.x * 32, n0 = blockIdx.y * 32;
    const int tx = threadIdx.x, ty = threadIdx.y;   // 32 x 8
    float s = 1.0f;
    if (aidx >= 0) {
        float e0 = __expf(alpha[0]), e1 = __expf(alpha[1]);
        s = (aidx == 0 ? e0 : e1) / (e0 + e1);
    }
#pragma unroll
    for (int j = 0; j < 32; j += 8) {
        int m = m0 + ty + j;
        float acc = 0.0f;
        for (int zz = 0; zz < Z; zz++)
            acc += parts[((size_t)zz * Min + m) * 512 + n0 + tx];
        tile[ty + j][tx] = acc * s;
    }
    __syncthreads();
#pragma unroll
    for (int j = 0; j < 32; j += 8) {
        float v = tile[tx][ty + j];
        __half h = __float2half_rn(v);
        size_t o = (size_t)(n0 + ty + j) * Min + m0 + tx;
        th[o] = h;
        if (tl) tl[o] = __float2half_rn(v - __half2float(h));
    }
}

// ------------------------- host -------------------------
extern "C" void kernel_launch(void* const* d_in, const int* in_sizes, int n_in,
                              void* d_out, int out_size)
{
    const float* x     = (const float*)d_in[0];
    const float* w     = (const float*)d_in[1];
    const float* alpha = (const float*)d_in[2];
    const float* bias  = (const float*)d_in[3];
    const float* s0    = (const float*)d_in[4];
    const float* s1    = (const float*)d_in[5];
    const float* s2    = (const float*)d_in[6];
    const float* s3    = (const float*)d_in[7];
    float* out = (float*)d_out;

    __half *xf, *s0f, *s1f, *s2f, *s3f;
    __half *Wth, *Wtl, *Pth, *T1h, *T3h;
    float *pP, *pT1p, *pT3p, *pOL;
    cudaGetSymbolAddress((void**)&xf,  g_xf);
    cudaGetSymbolAddress((void**)&s0f, g_s0f);
    cudaGetSymbolAddress((void**)&s1f, g_s1f);
    cudaGetSymbolAddress((void**)&s2f, g_s2f);
    cudaGetSymbolAddress((void**)&s3f, g_s3f);
    cudaGetSymbolAddress((void**)&Wth, g_Wth); cudaGetSymbolAddress((void**)&Wtl, g_Wtl);
    cudaGetSymbolAddress((void**)&Pth, g_Pth);
    cudaGetSymbolAddress((void**)&T1h, g_T1h);
    cudaGetSymbolAddress((void**)&T3h, g_T3h);
    cudaGetSymbolAddress((void**)&pP,  g_P);   cudaGetSymbolAddress((void**)&pT1p, g_T1p);
    cudaGetSymbolAddress((void**)&pT3p, g_T3p); cudaGetSymbolAddress((void**)&pOL, g_OL);

    cudaFuncSetAttribute((const void*)hgemm<false, 2>,
                         cudaFuncAttributeMaxDynamicSharedMemorySize, StageCfg<2>::SMEM);
    cudaFuncSetAttribute((const void*)hgemm<false, 1>,
                         cudaFuncAttributeMaxDynamicSharedMemorySize, StageCfg<1>::SMEM);
    cudaFuncSetAttribute((const void*)hgemm<true, 1>,
                         cudaFuncAttributeMaxDynamicSharedMemorySize, StageCfg<1>::SMEM);

    // One-time host-resource creation (first call = uncaptured correctness run;
    // no device-memory allocation involved). Same launch DAG every call.
    static cudaStream_t side = nullptr;
    static cudaEvent_t evRoot, evS3, evS1, evS0, evS2;
    if (!side) {
        cudaStreamCreateWithFlags(&side, cudaStreamNonBlocking);
        cudaEventCreateWithFlags(&evRoot, cudaEventDisableTiming);
        cudaEventCreateWithFlags(&evS3,   cudaEventDisableTiming);
        cudaEventCreateWithFlags(&evS1,   cudaEventDisableTiming);
        cudaEventCreateWithFlags(&evS0,   cudaEventDisableTiming);
        cudaEventCreateWithFlags(&evS2,   cudaEventDisableTiming);
    }

    // ---- fork: side stream converts the (dependency-free) s-matrices ----
    cudaEventRecord(evRoot, 0);
    cudaStreamWaitEvent(side, evRoot, 0);
    cvtA<<<2048, 256, 0, side>>>(s3, s3f, (size_t)NH * NN / 4);  cudaEventRecord(evS3, side);
    cvtA<<<1024, 256, 0, side>>>(s1, s1f, (size_t)KK * NN / 4);  cudaEventRecord(evS1, side);
    cvtA<<<1024, 256, 0, side>>>(s0, s0f, (size_t)NN * KK / 4);  cudaEventRecord(evS0, side);
    cvtA<<<2048, 256, 0, side>>>(s2, s2f, (size_t)NN * NH / 4);  cudaEventRecord(evS2, side);

    // ---- main stream: the dependent chain ----
    cvtA<<<1024, 256>>>(x, xf, (size_t)NN * DD / 4);
    cst<<<dim3(DD / 32, 16), dim3(32, 8)>>>(w, 1, DD, Wth, Wtl, alpha, -1);
    // G1: P = x @ W        [8192,512], K=512, 2-pass B
    hgemm<false, 2><<<dim3(4, 32, 1), 256, StageCfg<2>::SMEM>>>(xf, Wth, Wtl, pP,
                                                                NN, DD, nullptr, nullptr);
    cst<<<dim3(NN / 32, 16), dim3(32, 8)>>>(pP, 1, NN, Pth, nullptr, alpha, -1);
    // G4: T3 = s3 @ P      [6144,512], K=8192, split-K=3, 1-pass B
    cudaStreamWaitEvent(0, evS3, 0);
    hgemm<false, 1><<<dim3(4, 24, 3), 256, StageCfg<1>::SMEM>>>(s3f, Pth, nullptr,
                                                                pT3p, NH, NN, nullptr, nullptr);
    // G2: T1 = s1 @ P      [2048,512], K=8192, split-K=4, 1-pass B
    cudaStreamWaitEvent(0, evS1, 0);
    hgemm<false, 1><<<dim3(4, 8, 4), 256, StageCfg<1>::SMEM>>>(s1f, Pth, nullptr,
                                                               pT1p, KK, NN, nullptr, nullptr);
    cst<<<dim3(KK / 32, 16), dim3(32, 8)>>>(pT1p, 4, KK, T1h, nullptr, alpha, 0);
    // G3: OL = s0 @ T1     [8192,512], K=2048, 1-pass B
    cudaStreamWaitEvent(0, evS0, 0);
    hgemm<false, 1><<<dim3(4, 32, 1), 256, StageCfg<1>::SMEM>>>(s0f, T1h, nullptr, pOL,
                                                                NN, KK, nullptr, nullptr);
    cst<<<dim3(NH / 32, 16), dim3(32, 8)>>>(pT3p, 3, NH, T3h, nullptr, alpha, 1);
    // G5: out = relu(max(OL, s2 @ T3) + bias)   [8192,512], K=6144, 1-pass B
    // (evS2 wait also joins the side stream back into the origin stream)
    cudaStreamWaitEvent(0, evS2, 0);
    hgemm<true, 1><<<dim3(4, 32, 1), 256, StageCfg<1>::SMEM>>>(s2f, T3h, nullptr, out,
                                                               NN, NH, pOL, bias);
}

// round 13
// speedup vs baseline: 7.1531x; 1.0465x over previous
#include <cuda_runtime.h>
#include <cuda_fp16.h>
#include <cstdint>
#include <cstddef>

#define DINL __device__ __forceinline__

// ------------------------- problem sizes -------------------------
#define NN 8192
#define KK 2048
#define DD 512
#define NH (NN - KK)   // 6144

// ------------------------- scratch (static device globals) -------------------------
__device__ __half g_xf [NN*DD];
__device__ __half g_s0f[NN*KK];
__device__ __half g_s1f[KK*NN];
__device__ __half g_s2f[(size_t)NN*NH];
__device__ __half g_s3f[(size_t)NH*NN];
__device__ __half g_Wth[DD*DD],  g_Wtl[DD*DD];
__device__ __half g_Pth[DD*NN];
__device__ __half g_T1h[DD*KK];
__device__ __half g_T3h[DD*NH];
__device__ float g_P  [NN*DD];
__device__ float g_T1p[4*KK*DD];
__device__ float g_T3p[3*NH*DD];
__device__ float g_OL [NN*DD];

// ------------------------- ptx helpers (base ISA only) ----
DINL uint32_t smem_u32(const void* p) {
    uint32_t a;
    asm("{ .reg .u64 t; cvta.to.shared.u64 t, %1; cvt.u32.u64 %0, t; }" : "=r"(a) : "l"(p));
    return a;
}
DINL void cp16(uint32_t saddr, const void* g) {
    asm volatile("cp.async.cg.shared.global [%0], [%1], 16;" :: "r"(saddr), "l"(g));
}
DINL void cp_commit() { asm volatile("cp.async.commit_group;" ::: "memory"); }
DINL void cp_wait1()  { asm volatile("cp.async.wait_group 1;" ::: "memory"); }
DINL void cp_wait0()  { asm volatile("cp.async.wait_group 0;" ::: "memory"); }

DINL void ldsm4(uint32_t (&r)[4], uint32_t addr) {
    asm volatile("ldmatrix.sync.aligned.m8n8.x4.shared.b16 {%0,%1,%2,%3}, [%4];"
                 : "=r"(r[0]), "=r"(r[1]), "=r"(r[2]), "=r"(r[3]) : "r"(addr));
}
DINL void mma_f16(float (&d)[4], const uint32_t (&a)[4], const uint32_t* b) {
    asm volatile(
        "mma.sync.aligned.m16n8k16.row.col.f32.f16.f16.f32 "
        "{%0,%1,%2,%3}, {%4,%5,%6,%7}, {%8,%9}, {%0,%1,%2,%3};"
        : "+f"(d[0]), "+f"(d[1]), "+f"(d[2]), "+f"(d[3])
        : "r"(a[0]), "r"(a[1]), "r"(a[2]), "r"(a[3]), "r"(b[0]), "r"(b[1]));
}

// ------------------------- GEMM -------------------------
// C[z][M,512] = A[M,K] @ Bt^T, A single fp16; Bt fp16 hi(/lo) — NPASS∈{1,2}.
// CTA tile 256x128, BK=64 (128B SW128 rows), 8 warps of 64x64, 2-stage cp.async.
static constexpr int OFF_A  = 0;       // 32 KB (256 rows x 128B)
static constexpr int OFF_BH = 32768;   // 16 KB
static constexpr int OFF_BL = 49152;   // 16 KB (NPASS==2 only)

template <int NPASS> struct StageCfg {
    static constexpr int STAGE = (NPASS == 2) ? 65536 : 49152;
    static constexpr int SMEM  = 2 * STAGE;
};

DINL void ld_sec(uint32_t sdst, const char* src, int row0, size_t pitch,
                 size_t kbyte, int nIter, int tid)
{
    for (int i = 0; i < nIter; i++) {
        int idx = tid * 16 + i * 4096;
        int row = idx >> 7, col = idx & 127;
        uint32_t sw = (uint32_t)idx ^ (((uint32_t)idx >> 3) & 0x70);
        cp16(sdst + sw, src + (size_t)(row0 + row) * pitch + kbyte + col);
    }
}

template <bool FINAL, int NPASS>
__global__ void __launch_bounds__(256, 1)
hgemm(const __half* __restrict__ A_,
      const __half* __restrict__ Bh_, const __half* __restrict__ Bl_,
      float* __restrict__ C, int M, int K,
      const float* __restrict__ other, const float* __restrict__ bias)
{
    constexpr int STAGE_BYTES = StageCfg<NPASS>::STAGE;
    extern __shared__ char smem[];
    const uint32_t sb0 = smem_u32(smem);
    const int tid = threadIdx.x, wid = tid >> 5, lane = tid & 31;
    const int brow = blockIdx.y * 256, bcol = blockIdx.x * 128;
    const int warpM = (wid & 3) * 64, warpN = (wid >> 2) * 64;

    const int kchunks = K >> 6;
    const int Z = gridDim.z, z = blockIdx.z;
    const int kc0 = (int)(((long long)kchunks * z) / Z);
    const int kc1 = (int)(((long long)kchunks * (z + 1)) / Z);
    const int total = kc1 - kc0;
    float* Cz = C + (size_t)z * M * 512;

    const char* A  = (const char*)A_;
    const char* Bh = (const char*)Bh_;
    const char* Bl = (const char*)Bl_;
    const size_t pitch = (size_t)K * 2;

    const uint32_t xorv = (uint32_t)(lane & 7) << 4;
    const uint32_t kaA = ((lane >> 4) & 1) * 16;
    const uint32_t kbB = ((lane >> 3) & 1) * 16;
    uint32_t aRowOff[4], bRowOff[4];
#pragma unroll
    for (int am = 0; am < 4; am++)
        aRowOff[am] = (uint32_t)(warpM + am * 16 + (lane & 15)) * 128;
#pragma unroll
    for (int bg = 0; bg < 4; bg++)
        bRowOff[bg] = (uint32_t)(warpN + bg * 16 + ((lane >> 4) & 1) * 8 + (lane & 7)) * 128;

    float acc[4][8][4];
#pragma unroll
    for (int i = 0; i < 4; i++)
#pragma unroll
        for (int j = 0; j < 8; j++)
#pragma unroll
            for (int t = 0; t < 4; t++) acc[i][j][t] = 0.0f;

    // pipeline prologue: fill both stages
#pragma unroll 1
    for (int p = 0; p < 2; p++) {
        uint32_t sb = sb0 + p * STAGE_BYTES;
        size_t kb = (size_t)(kc0 + p) * 128;
        ld_sec(sb + OFF_A,  A,  brow, pitch, kb, 8, tid);
        ld_sec(sb + OFF_BH, Bh, bcol, pitch, kb, 4, tid);
        if (NPASS == 2) ld_sec(sb + OFF_BL, Bl, bcol, pitch, kb, 4, tid);
        cp_commit();
    }

#pragma unroll 1
    for (int it = 0; it < total; ++it) {
        const int s = it & 1;
        if (it < total - 1) cp_wait1(); else cp_wait0();
        __syncthreads();

        const uint32_t sb = sb0 + s * STAGE_BYTES;
#pragma unroll 1
        for (int ks = 0; ks < 4; ks++) {
            const uint32_t kA = ((uint32_t)(ks * 32) + kaA) ^ xorv;
            const uint32_t kB = ((uint32_t)(ks * 32) + kbB) ^ xorv;
            uint32_t ah[4][4];
#pragma unroll
            for (int am = 0; am < 4; am++)
                ldsm4(ah[am], sb + OFF_A + aRowOff[am] + kA);
#pragma unroll
            for (int bg = 0; bg < 4; bg++) {
                uint32_t bh[4], bl[4];
                ldsm4(bh, sb + OFF_BH + bRowOff[bg] + kB);
                if (NPASS == 2) ldsm4(bl, sb + OFF_BL + bRowOff[bg] + kB);
#pragma unroll
                for (int am = 0; am < 4; am++)
#pragma unroll
                    for (int h = 0; h < 2; h++)
                        mma_f16(acc[am][bg * 2 + h], ah[am], bh + h * 2);
                if (NPASS == 2) {
#pragma unroll
                    for (int am = 0; am < 4; am++)
#pragma unroll
                        for (int h = 0; h < 2; h++)
                            mma_f16(acc[am][bg * 2 + h], ah[am], bl + h * 2);
                }
            }
        }
        __syncthreads();
        const int nx = it + 2;
        if (nx < total) {
            size_t kb = (size_t)(kc0 + nx) * 128;
            ld_sec(sb + OFF_A,  A,  brow, pitch, kb, 8, tid);
            ld_sec(sb + OFF_BH, Bh, bcol, pitch, kb, 4, tid);
            if (NPASS == 2) ld_sec(sb + OFF_BL, Bl, bcol, pitch, kb, 4, tid);
            cp_commit();
        }
    }

    // epilogue
#pragma unroll
    for (int am = 0; am < 4; am++) {
#pragma unroll
        for (int bn = 0; bn < 8; bn++) {
            const int r0 = brow + warpM + am * 16 + (lane >> 2);
            const int cg = bcol + warpN + bn * 8 + (lane & 3) * 2;
#pragma unroll
            for (int h = 0; h < 2; h++) {
                const int row = r0 + h * 8;
                float2 v = make_float2(acc[am][bn][h * 2], acc[am][bn][h * 2 + 1]);
                size_t o = (size_t)row * 512 + cg;
                if (FINAL) {
                    float2 ov = *(const float2*)(other + o);
                    float2 bb = *(const float2*)(bias + cg);
                    v.x = fmaxf(fmaxf(v.x, ov.x) + bb.x, 0.0f);
                    v.y = fmaxf(fmaxf(v.y, ov.y) + bb.y, 0.0f);
                }
                *(float2*)(Cz + o) = v;
            }
        }
    }
}

// ------------------------- convert fp32 -> fp16 (A operands) -------------------------
__global__ void cvtA(const float* __restrict__ src, __half* __restrict__ dst, size_t n4)
{
    size_t stride = (size_t)gridDim.x * blockDim.x;
    for (size_t i = (size_t)blockIdx.x * blockDim.x + threadIdx.x; i < n4; i += stride) {
        float4 v = ((const float4*)src)[i];
        __half2 p0 = __floats2half2_rn(v.x, v.y);
        __half2 p1 = __floats2half2_rn(v.z, v.w);
        uint2 o;
        o.x = *(const uint32_t*)&p0;
        o.y = *(const uint32_t*)&p1;
        ((uint2*)dst)[i] = o;
    }
}

// ------------- combine(split-K) + scale + transpose + fp16 (hi, optional lo) -------------
__global__ void cst(const float* __restrict__ parts, int Z, int Min,
                    __half* __restrict__ th, __half* __restrict__ tl,
                    const float* __restrict__ alpha, int aidx)
{
    __shared__ float tile[32][33];
    const int m0 = blockIdx.x * 32, n0 = blockIdx.y * 32;
    const int tx = threadIdx.x, ty = threadIdx.y;   // 32 x 8
    float s = 1.0f;
    if (aidx >= 0) {
        float e0 = __expf(alpha[0]), e1 = __expf(alpha[1]);
        s = (aidx == 0 ? e0 : e1) / (e0 + e1);
    }
#pragma unroll
    for (int j = 0; j < 32; j += 8) {
        int m = m0 + ty + j;
        float acc = 0.0f;
        for (int zz = 0; zz < Z; zz++)
            acc += parts[((size_t)zz * Min + m) * 512 + n0 + tx];
        tile[ty + j][tx] = acc * s;
    }
    __syncthreads();
#pragma unroll
    for (int j = 0; j < 32; j += 8) {
        float v = tile[tx][ty + j];
        __half h = __float2half_rn(v);
        size_t o = (size_t)(n0 + ty + j) * Min + m0 + tx;
        th[o] = h;
        if (tl) tl[o] = __float2half_rn(v - __half2float(h));
    }
}

// ------------------------- host -------------------------
extern "C" void kernel_launch(void* const* d_in, const int* in_sizes, int n_in,
                              void* d_out, int out_size)
{
    const float* x     = (const float*)d_in[0];
    const float* w     = (const float*)d_in[1];
    const float* alpha = (const float*)d_in[2];
    const float* bias  = (const float*)d_in[3];
    const float* s0    = (const float*)d_in[4];
    const float* s1    = (const float*)d_in[5];
    const float* s2    = (const float*)d_in[6];
    const float* s3    = (const float*)d_in[7];
    float* out = (float*)d_out;

    __half *xf, *s0f, *s1f, *s2f, *s3f;
    __half *Wth, *Wtl, *Pth, *T1h, *T3h;
    float *pP, *pT1p, *pT3p, *pOL;
    cudaGetSymbolAddress((void**)&xf,  g_xf);
    cudaGetSymbolAddress((void**)&s0f, g_s0f);
    cudaGetSymbolAddress((void**)&s1f, g_s1f);
    cudaGetSymbolAddress((void**)&s2f, g_s2f);
    cudaGetSymbolAddress((void**)&s3f, g_s3f);
    cudaGetSymbolAddress((void**)&Wth, g_Wth); cudaGetSymbolAddress((void**)&Wtl, g_Wtl);
    cudaGetSymbolAddress((void**)&Pth, g_Pth);
    cudaGetSymbolAddress((void**)&T1h, g_T1h);
    cudaGetSymbolAddress((void**)&T3h, g_T3h);
    cudaGetSymbolAddress((void**)&pP,  g_P);   cudaGetSymbolAddress((void**)&pT1p, g_T1p);
    cudaGetSymbolAddress((void**)&pT3p, g_T3p); cudaGetSymbolAddress((void**)&pOL, g_OL);

    cudaFuncSetAttribute((const void*)hgemm<false, 2>,
                         cudaFuncAttributeMaxDynamicSharedMemorySize, StageCfg<2>::SMEM);
    cudaFuncSetAttribute((const void*)hgemm<false, 1>,
                         cudaFuncAttributeMaxDynamicSharedMemorySize, StageCfg<1>::SMEM);
    cudaFuncSetAttribute((const void*)hgemm<true, 1>,
                         cudaFuncAttributeMaxDynamicSharedMemorySize, StageCfg<1>::SMEM);

    // One-time host-resource creation (first call = uncaptured correctness run).
    static cudaStream_t side = nullptr, side2 = nullptr;
    static cudaEvent_t evRoot, evS3, evS1, evS0, evS2, evP, evG3;
    if (!side) {
        cudaStreamCreateWithFlags(&side,  cudaStreamNonBlocking);
        cudaStreamCreateWithFlags(&side2, cudaStreamNonBlocking);
        cudaEventCreateWithFlags(&evRoot, cudaEventDisableTiming);
        cudaEventCreateWithFlags(&evS3,   cudaEventDisableTiming);
        cudaEventCreateWithFlags(&evS1,   cudaEventDisableTiming);
        cudaEventCreateWithFlags(&evS0,   cudaEventDisableTiming);
        cudaEventCreateWithFlags(&evS2,   cudaEventDisableTiming);
        cudaEventCreateWithFlags(&evP,    cudaEventDisableTiming);
        cudaEventCreateWithFlags(&evG3,   cudaEventDisableTiming);
    }

    // ---- fork: side stream converts the (dependency-free) s-matrices ----
    cudaEventRecord(evRoot, 0);
    cudaStreamWaitEvent(side, evRoot, 0);
    cvtA<<<2048, 256, 0, side>>>(s3, s3f, (size_t)NH * NN / 4);  cudaEventRecord(evS3, side);
    cvtA<<<1024, 256, 0, side>>>(s1, s1f, (size_t)KK * NN / 4);  cudaEventRecord(evS1, side);
    cvtA<<<1024, 256, 0, side>>>(s0, s0f, (size_t)NN * KK / 4);  cudaEventRecord(evS0, side);
    cvtA<<<2048, 256, 0, side>>>(s2, s2f, (size_t)NN * NH / 4);  cudaEventRecord(evS2, side);

    // ---- main stream: x/W prep + G1 + P transpose ----
    cvtA<<<1024, 256>>>(x, xf, (size_t)NN * DD / 4);
    cst<<<dim3(DD / 32, 16), dim3(32, 8)>>>(w, 1, DD, Wth, Wtl, alpha, -1);
    // G1: P = x @ W        [8192,512], K=512, 2-pass B
    hgemm<false, 2><<<dim3(4, 32, 1), 256, StageCfg<2>::SMEM>>>(xf, Wth, Wtl, pP,
                                                                NN, DD, nullptr, nullptr);
    cst<<<dim3(NN / 32, 16), dim3(32, 8)>>>(pP, 1, NN, Pth, nullptr, alpha, -1);
    cudaEventRecord(evP, 0);

    // ---- chain B (side2): G2 -> cstT1 -> G3 (produces OL) ----
    cudaStreamWaitEvent(side2, evP, 0);
    cudaStreamWaitEvent(side2, evS1, 0);
    // G2: T1 = s1 @ P      [2048,512], K=8192, split-K=4, 1-pass B
    hgemm<false, 1><<<dim3(4, 8, 4), 256, StageCfg<1>::SMEM, side2>>>(
        s1f, Pth, nullptr, pT1p, KK, NN, nullptr, nullptr);
    cst<<<dim3(KK / 32, 16), dim3(32, 8), 0, side2>>>(pT1p, 4, KK, T1h, nullptr, alpha, 0);
    cudaStreamWaitEvent(side2, evS0, 0);
    // G3: OL = s0 @ T1     [8192,512], K=2048, 1-pass B
    hgemm<false, 1><<<dim3(4, 32, 1), 256, StageCfg<1>::SMEM, side2>>>(
        s0f, T1h, nullptr, pOL, NN, KK, nullptr, nullptr);
    cudaEventRecord(evG3, side2);

    // ---- chain A (main): G4 -> cstT3 ----
    cudaStreamWaitEvent(0, evS3, 0);
    // G4: T3 = s3 @ P      [6144,512], K=8192, split-K=3, 1-pass B
    hgemm<false, 1><<<dim3(4, 24, 3), 256, StageCfg<1>::SMEM>>>(s3f, Pth, nullptr,
                                                                pT3p, NH, NN, nullptr, nullptr);
    cst<<<dim3(NH / 32, 16), dim3(32, 8)>>>(pT3p, 3, NH, T3h, nullptr, alpha, 1);

    // ---- join: G5 needs T3h (main), OL (side2), s2f (side) ----
    cudaStreamWaitEvent(0, evG3, 0);
    cudaStreamWaitEvent(0, evS2, 0);
    // G5: out = relu(max(OL, s2 @ T3) + bias)   [8192,512], K=6144, 1-pass B
    hgemm<true, 1><<<dim3(4, 32, 1), 256, StageCfg<1>::SMEM>>>(s2f, T3h, nullptr, out,
                                                               NN, NH, pOL, bias);
}

// round 14
// speedup vs baseline: 7.4472x; 1.0411x over previous
#include <cuda_runtime.h>
#include <cuda_fp16.h>
#include <cstdint>
#include <cstddef>

#define DINL __device__ __forceinline__

// ------------------------- problem sizes -------------------------
#define NN 8192
#define KK 2048
#define DD 512
#define NH (NN - KK)   // 6144

// ------------------------- scratch (static device globals) -------------------------
__device__ __half g_xf [NN*DD];
__device__ __half g_s0f[NN*KK];
__device__ __half g_s1f[KK*NN];
__device__ __half g_s2f[(size_t)NN*NH];
__device__ __half g_s3f[(size_t)NH*NN];
__device__ __half g_Wth[DD*DD],  g_Wtl[DD*DD];
__device__ __half g_Pth[DD*NN];
__device__ __half g_T1h[DD*KK];
__device__ __half g_T3h[DD*NH];
__device__ float g_T1p[4*KK*DD];
__device__ float g_T3p[3*NH*DD];
__device__ float g_OL [NN*DD];

// ------------------------- ptx helpers (base ISA only) ----
DINL uint32_t smem_u32(const void* p) {
    uint32_t a;
    asm("{ .reg .u64 t; cvta.to.shared.u64 t, %1; cvt.u32.u64 %0, t; }" : "=r"(a) : "l"(p));
    return a;
}
DINL void cp16(uint32_t saddr, const void* g) {
    asm volatile("cp.async.cg.shared.global [%0], [%1], 16;" :: "r"(saddr), "l"(g));
}
DINL void cp_commit() { asm volatile("cp.async.commit_group;" ::: "memory"); }
DINL void cp_wait1()  { asm volatile("cp.async.wait_group 1;" ::: "memory"); }
DINL void cp_wait0()  { asm volatile("cp.async.wait_group 0;" ::: "memory"); }

DINL void ldsm4(uint32_t (&r)[4], uint32_t addr) {
    asm volatile("ldmatrix.sync.aligned.m8n8.x4.shared.b16 {%0,%1,%2,%3}, [%4];"
                 : "=r"(r[0]), "=r"(r[1]), "=r"(r[2]), "=r"(r[3]) : "r"(addr));
}
DINL void mma_f16(float (&d)[4], const uint32_t (&a)[4], const uint32_t* b) {
    asm volatile(
        "mma.sync.aligned.m16n8k16.row.col.f32.f16.f16.f32 "
        "{%0,%1,%2,%3}, {%4,%5,%6,%7}, {%8,%9}, {%0,%1,%2,%3};"
        : "+f"(d[0]), "+f"(d[1]), "+f"(d[2]), "+f"(d[3])
        : "r"(a[0]), "r"(a[1]), "r"(a[2]), "r"(a[3]), "r"(b[0]), "r"(b[1]));
}

// ------------------------- GEMM -------------------------
// C[z][M,512] = A[M,K] @ Bt^T, A single fp16; Bt fp16 hi(/lo) — NPASS∈{1,2}.
// TRANSP: skip fp32 C; write fp16 transposed output Ct[512, M] via smem staging.
// CTA tile 256x128, BK=64 (128B SW128 rows), 8 warps of 64x64, 2-stage cp.async.
static constexpr int OFF_A  = 0;       // 32 KB (256 rows x 128B)
static constexpr int OFF_BH = 32768;   // 16 KB
static constexpr int OFF_BL = 49152;   // 16 KB (NPASS==2 only)

template <int NPASS> struct StageCfg {
    static constexpr int STAGE = (NPASS == 2) ? 65536 : 49152;
    static constexpr int SMEM  = 2 * STAGE;
};

DINL void ld_sec(uint32_t sdst, const char* src, int row0, size_t pitch,
                 size_t kbyte, int nIter, int tid)
{
    for (int i = 0; i < nIter; i++) {
        int idx = tid * 16 + i * 4096;
        int row = idx >> 7, col = idx & 127;
        uint32_t sw = (uint32_t)idx ^ (((uint32_t)idx >> 3) & 0x70);
        cp16(sdst + sw, src + (size_t)(row0 + row) * pitch + kbyte + col);
    }
}

template <bool FINAL, int NPASS, bool TRANSP>
__global__ void __launch_bounds__(256, 1)
hgemm(const __half* __restrict__ A_,
      const __half* __restrict__ Bh_, const __half* __restrict__ Bl_,
      float* __restrict__ C, __half* __restrict__ Ct, int M, int K,
      const float* __restrict__ other, const float* __restrict__ bias)
{
    constexpr int STAGE_BYTES = StageCfg<NPASS>::STAGE;
    extern __shared__ char smem[];
    const uint32_t sb0 = smem_u32(smem);
    const int tid = threadIdx.x, wid = tid >> 5, lane = tid & 31;
    const int brow = blockIdx.y * 256, bcol = blockIdx.x * 128;
    const int warpM = (wid & 3) * 64, warpN = (wid >> 2) * 64;

    const int kchunks = K >> 6;
    const int Z = gridDim.z, z = blockIdx.z;
    const int kc0 = (int)(((long long)kchunks * z) / Z);
    const int kc1 = (int)(((long long)kchunks * (z + 1)) / Z);
    const int total = kc1 - kc0;
    float* Cz = C + (size_t)z * M * 512;

    const char* A  = (const char*)A_;
    const char* Bh = (const char*)Bh_;
    const char* Bl = (const char*)Bl_;
    const size_t pitch = (size_t)K * 2;

    const uint32_t xorv = (uint32_t)(lane & 7) << 4;
    const uint32_t kaA = ((lane >> 4) & 1) * 16;
    const uint32_t kbB = ((lane >> 3) & 1) * 16;
    uint32_t aRowOff[4], bRowOff[4];
#pragma unroll
    for (int am = 0; am < 4; am++)
        aRowOff[am] = (uint32_t)(warpM + am * 16 + (lane & 15)) * 128;
#pragma unroll
    for (int bg = 0; bg < 4; bg++)
        bRowOff[bg] = (uint32_t)(warpN + bg * 16 + ((lane >> 4) & 1) * 8 + (lane & 7)) * 128;

    float acc[4][8][4];
#pragma unroll
    for (int i = 0; i < 4; i++)
#pragma unroll
        for (int j = 0; j < 8; j++)
#pragma unroll
            for (int t = 0; t < 4; t++) acc[i][j][t] = 0.0f;

    // pipeline prologue: fill both stages
#pragma unroll 1
    for (int p = 0; p < 2; p++) {
        uint32_t sb = sb0 + p * STAGE_BYTES;
        size_t kb = (size_t)(kc0 + p) * 128;
        ld_sec(sb + OFF_A,  A,  brow, pitch, kb, 8, tid);
        ld_sec(sb + OFF_BH, Bh, bcol, pitch, kb, 4, tid);
        if (NPASS == 2) ld_sec(sb + OFF_BL, Bl, bcol, pitch, kb, 4, tid);
        cp_commit();
    }

#pragma unroll 1
    for (int it = 0; it < total; ++it) {
        const int s = it & 1;
        if (it < total - 1) cp_wait1(); else cp_wait0();
        __syncthreads();

        const uint32_t sb = sb0 + s * STAGE_BYTES;
#pragma unroll 1
        for (int ks = 0; ks < 4; ks++) {
            const uint32_t kA = ((uint32_t)(ks * 32) + kaA) ^ xorv;
            const uint32_t kB = ((uint32_t)(ks * 32) + kbB) ^ xorv;
            uint32_t ah[4][4];
#pragma unroll
            for (int am = 0; am < 4; am++)
                ldsm4(ah[am], sb + OFF_A + aRowOff[am] + kA);
#pragma unroll
            for (int bg = 0; bg < 4; bg++) {
                uint32_t bh[4], bl[4];
                ldsm4(bh, sb + OFF_BH + bRowOff[bg] + kB);
                if (NPASS == 2) ldsm4(bl, sb + OFF_BL + bRowOff[bg] + kB);
#pragma unroll
                for (int am = 0; am < 4; am++)
#pragma unroll
                    for (int h = 0; h < 2; h++)
                        mma_f16(acc[am][bg * 2 + h], ah[am], bh + h * 2);
                if (NPASS == 2) {
#pragma unroll
                    for (int am = 0; am < 4; am++)
#pragma unroll
                        for (int h = 0; h < 2; h++)
                            mma_f16(acc[am][bg * 2 + h], ah[am], bl + h * 2);
                }
            }
        }
        __syncthreads();
        const int nx = it + 2;
        if (nx < total) {
            size_t kb = (size_t)(kc0 + nx) * 128;
            ld_sec(sb + OFF_A,  A,  brow, pitch, kb, 8, tid);
            ld_sec(sb + OFF_BH, Bh, bcol, pitch, kb, 4, tid);
            if (NPASS == 2) ld_sec(sb + OFF_BL, Bl, bcol, pitch, kb, 4, tid);
            cp_commit();
        }
    }

    if (TRANSP) {
        // Fused transpose + fp16 epilogue: stage tr[c][r] (c=0..127 local col,
        // r=0..255 local row) in smem with stride 264, then coalesced store.
        __syncthreads();                 // all warps done reading stage smem
        __half* tr = (__half*)smem;
#pragma unroll
        for (int am = 0; am < 4; am++) {
#pragma unroll
            for (int bn = 0; bn < 8; bn++) {
                const int r0 = warpM + am * 16 + (lane >> 2);
                const int c0 = warpN + bn * 8 + (lane & 3) * 2;
#pragma unroll
                for (int h = 0; h < 2; h++) {
                    const int r = r0 + h * 8;
                    tr[(c0    ) * 264 + r] = __float2half_rn(acc[am][bn][h * 2]);
                    tr[(c0 + 1) * 264 + r] = __float2half_rn(acc[am][bn][h * 2 + 1]);
                }
            }
        }
        __syncthreads();
        const int c = tid >> 1, j0 = (tid & 1) * 128;
        __half* gdst = Ct + (size_t)(bcol + c) * M + brow + j0;
        const __half* srow = tr + c * 264 + j0;
#pragma unroll
        for (int t = 0; t < 16; t++)
            *(uint4*)(gdst + t * 8) = *(const uint4*)(srow + t * 8);
        return;
    }

    // standard epilogue
#pragma unroll
    for (int am = 0; am < 4; am++) {
#pragma unroll
        for (int bn = 0; bn < 8; bn++) {
            const int r0 = brow + warpM + am * 16 + (lane >> 2);
            const int cg = bcol + warpN + bn * 8 + (lane & 3) * 2;
#pragma unroll
            for (int h = 0; h < 2; h++) {
                const int row = r0 + h * 8;
                float2 v = make_float2(acc[am][bn][h * 2], acc[am][bn][h * 2 + 1]);
                size_t o = (size_t)row * 512 + cg;
                if (FINAL) {
                    float2 ov = *(const float2*)(other + o);
                    float2 bb = *(const float2*)(bias + cg);
                    v.x = fmaxf(fmaxf(v.x, ov.x) + bb.x, 0.0f);
                    v.y = fmaxf(fmaxf(v.y, ov.y) + bb.y, 0.0f);
                }
                *(float2*)(Cz + o) = v;
            }
        }
    }
}

// ------------------------- convert fp32 -> fp16 (A operands) -------------------------
__global__ void cvtA(const float* __restrict__ src, __half* __restrict__ dst, size_t n4)
{
    size_t stride = (size_t)gridDim.x * blockDim.x;
    for (size_t i = (size_t)blockIdx.x * blockDim.x + threadIdx.x; i < n4; i += stride) {
        float4 v = ((const float4*)src)[i];
        __half2 p0 = __floats2half2_rn(v.x, v.y);
        __half2 p1 = __floats2half2_rn(v.z, v.w);
        uint2 o;
        o.x = *(const uint32_t*)&p0;
        o.y = *(const uint32_t*)&p1;
        ((uint2*)dst)[i] = o;
    }
}

// ------------- combine(split-K) + scale + transpose + fp16 (hi, optional lo) -------------
__global__ void cst(const float* __restrict__ parts, int Z, int Min,
                    __half* __restrict__ th, __half* __restrict__ tl,
                    const float* __restrict__ alpha, int aidx)
{
    __shared__ float tile[32][33];
    const int m0 = blockIdx.x * 32, n0 = blockIdx.y * 32;
    const int tx = threadIdx.x, ty = threadIdx.y;   // 32 x 8
    float s = 1.0f;
    if (aidx >= 0) {
        float e0 = __expf(alpha[0]), e1 = __expf(alpha[1]);
        s = (aidx == 0 ? e0 : e1) / (e0 + e1);
    }
#pragma unroll
    for (int j = 0; j < 32; j += 8) {
        int m = m0 + ty + j;
        float acc = 0.0f;
        for (int zz = 0; zz < Z; zz++)
            acc += parts[((size_t)zz * Min + m) * 512 + n0 + tx];
        tile[ty + j][tx] = acc * s;
    }
    __syncthreads();
#pragma unroll
    for (int j = 0; j < 32; j += 8) {
        float v = tile[tx][ty + j];
        __half h = __float2half_rn(v);
        size_t o = (size_t)(n0 + ty + j) * Min + m0 + tx;
        th[o] = h;
        if (tl) tl[o] = __float2half_rn(v - __half2float(h));
    }
}

// ------------------------- host -------------------------
extern "C" void kernel_launch(void* const* d_in, const int* in_sizes, int n_in,
                              void* d_out, int out_size)
{
    const float* x     = (const float*)d_in[0];
    const float* w     = (const float*)d_in[1];
    const float* alpha = (const float*)d_in[2];
    const float* bias  = (const float*)d_in[3];
    const float* s0    = (const float*)d_in[4];
    const float* s1    = (const float*)d_in[5];
    const float* s2    = (const float*)d_in[6];
    const float* s3    = (const float*)d_in[7];
    float* out = (float*)d_out;

    __half *xf, *s0f, *s1f, *s2f, *s3f;
    __half *Wth, *Wtl, *Pth, *T1h, *T3h;
    float *pT1p, *pT3p, *pOL;
    cudaGetSymbolAddress((void**)&xf,  g_xf);
    cudaGetSymbolAddress((void**)&s0f, g_s0f);
    cudaGetSymbolAddress((void**)&s1f, g_s1f);
    cudaGetSymbolAddress((void**)&s2f, g_s2f);
    cudaGetSymbolAddress((void**)&s3f, g_s3f);
    cudaGetSymbolAddress((void**)&Wth, g_Wth); cudaGetSymbolAddress((void**)&Wtl, g_Wtl);
    cudaGetSymbolAddress((void**)&Pth, g_Pth);
    cudaGetSymbolAddress((void**)&T1h, g_T1h);
    cudaGetSymbolAddress((void**)&T3h, g_T3h);
    cudaGetSymbolAddress((void**)&pT1p, g_T1p);
    cudaGetSymbolAddress((void**)&pT3p, g_T3p); cudaGetSymbolAddress((void**)&pOL, g_OL);

    cudaFuncSetAttribute((const void*)hgemm<false, 2, true>,
                         cudaFuncAttributeMaxDynamicSharedMemorySize, StageCfg<2>::SMEM);
    cudaFuncSetAttribute((const void*)hgemm<false, 1, false>,
                         cudaFuncAttributeMaxDynamicSharedMemorySize, StageCfg<1>::SMEM);
    cudaFuncSetAttribute((const void*)hgemm<true, 1, false>,
                         cudaFuncAttributeMaxDynamicSharedMemorySize, StageCfg<1>::SMEM);

    // One-time host-resource creation (first call = uncaptured correctness run).
    static cudaStream_t side = nullptr, side2 = nullptr;
    static cudaEvent_t evRoot, evS3, evS1, evS0, evS2, evP, evG3;
    if (!side) {
        cudaStreamCreateWithFlags(&side,  cudaStreamNonBlocking);
        cudaStreamCreateWithFlags(&side2, cudaStreamNonBlocking);
        cudaEventCreateWithFlags(&evRoot, cudaEventDisableTiming);
        cudaEventCreateWithFlags(&evS3,   cudaEventDisableTiming);
        cudaEventCreateWithFlags(&evS1,   cudaEventDisableTiming);
        cudaEventCreateWithFlags(&evS0,   cudaEventDisableTiming);
        cudaEventCreateWithFlags(&evS2,   cudaEventDisableTiming);
        cudaEventCreateWithFlags(&evP,    cudaEventDisableTiming);
        cudaEventCreateWithFlags(&evG3,   cudaEventDisableTiming);
    }

    // ---- fork: side stream converts the (dependency-free) s-matrices ----
    cudaEventRecord(evRoot, 0);
    cudaStreamWaitEvent(side, evRoot, 0);
    cvtA<<<2048, 256, 0, side>>>(s3, s3f, (size_t)NH * NN / 4);  cudaEventRecord(evS3, side);
    cvtA<<<1024, 256, 0, side>>>(s1, s1f, (size_t)KK * NN / 4);  cudaEventRecord(evS1, side);
    cvtA<<<1024, 256, 0, side>>>(s0, s0f, (size_t)NN * KK / 4);  cudaEventRecord(evS0, side);
    cvtA<<<2048, 256, 0, side>>>(s2, s2f, (size_t)NN * NH / 4);  cudaEventRecord(evS2, side);

    // ---- main stream: x/W prep + G1 (fused transposed epilogue -> Pth) ----
    cvtA<<<1024, 256>>>(x, xf, (size_t)NN * DD / 4);
    cst<<<dim3(DD / 32, 16), dim3(32, 8)>>>(w, 1, DD, Wth, Wtl, alpha, -1);
    // G1: Pth = (x @ W)^T fp16   [512,8192], K=512, 2-pass B, fused transpose
    hgemm<false, 2, true><<<dim3(4, 32, 1), 256, StageCfg<2>::SMEM>>>(
        xf, Wth, Wtl, nullptr, Pth, NN, DD, nullptr, nullptr);
    cudaEventRecord(evP, 0);

    // ---- chain B (side2): G2 -> cstT1 -> G3 (produces OL) ----
    cudaStreamWaitEvent(side2, evP, 0);
    cudaStreamWaitEvent(side2, evS1, 0);
    // G2: T1 = s1 @ P      [2048,512], K=8192, split-K=4, 1-pass B
    hgemm<false, 1, false><<<dim3(4, 8, 4), 256, StageCfg<1>::SMEM, side2>>>(
        s1f, Pth, nullptr, pT1p, nullptr, KK, NN, nullptr, nullptr);
    cst<<<dim3(KK / 32, 16), dim3(32, 8), 0, side2>>>(pT1p, 4, KK, T1h, nullptr, alpha, 0);
    cudaStreamWaitEvent(side2, evS0, 0);
    // G3: OL = s0 @ T1     [8192,512], K=2048, 1-pass B
    hgemm<false, 1, false><<<dim3(4, 32, 1), 256, StageCfg<1>::SMEM, side2>>>(
        s0f, T1h, nullptr, pOL, nullptr, NN, KK, nullptr, nullptr);
    cudaEventRecord(evG3, side2);

    // ---- chain A (main): G4 -> cstT3 ----
    cudaStreamWaitEvent(0, evS3, 0);
    // G4: T3 = s3 @ P      [6144,512], K=8192, split-K=3, 1-pass B
    hgemm<false, 1, false><<<dim3(4, 24, 3), 256, StageCfg<1>::SMEM>>>(
        s3f, Pth, nullptr, pT3p, nullptr, NH, NN, nullptr, nullptr);
    cst<<<dim3(NH / 32, 16), dim3(32, 8)>>>(pT3p, 3, NH, T3h, nullptr, alpha, 1);

    // ---- join: G5 needs T3h (main), OL (side2), s2f (side) ----
    cudaStreamWaitEvent(0, evG3, 0);
    cudaStreamWaitEvent(0, evS2, 0);
    // G5: out = relu(max(OL, s2 @ T3) + bias)   [8192,512], K=6144, 1-pass B
    hgemm<true, 1, false><<<dim3(4, 32, 1), 256, StageCfg<1>::SMEM>>>(
        s2f, T3h, nullptr, out, nullptr, NN, NH, pOL, bias);
}